// round 12
// baseline (speedup 1.0000x reference)
#include <cuda_runtime.h>
#include <math.h>

// ---------------- problem constants ----------------
#define BB   4
#define CX   256
#define HX   32
#define HY   65
#define NPIX (HY*HY)   // 4225
#define CG   128
#define KD   32
#define NBHW 16900.0f
#define EPSB 1e-5f

// padded plane layout: pitch 68 floats (16B-aligned rows), 65 data rows +
// 1 pad row per plane; header in front. Pads are NEVER written -> stay 0.
#define PP    68
#define PSTR  (66*PP)     // 4488 floats per plane
#define HDR   (PP + 4)
#define NGRP  17          // col groups of 4 per row
#define JOBS5 (HY*NGRP)   // 1105

typedef unsigned long long ull;

// ---------------- packed f32x2 helpers ----------------
__device__ __forceinline__ ull pack2(float a, float b) {
    ull r; asm("mov.b64 %0, {%1,%2};" : "=l"(r) : "f"(a), "f"(b)); return r;
}
__device__ __forceinline__ ull bcast2(float a) { return pack2(a, a); }
__device__ __forceinline__ void unpack2(ull v, float& a, float& b) {
    asm("mov.b64 {%0,%1}, %2;" : "=f"(a), "=f"(b) : "l"(v));
}
__device__ __forceinline__ ull fma2(ull a, ull b, ull c) {
    ull d; asm("fma.rn.f32x2 %0, %1, %2, %3;" : "=l"(d) : "l"(a), "l"(b), "l"(c)); return d;
}

// ---------------- scratch (zero-initialized .bss; pads stay 0) -----------
__device__ __align__(16) float g_h  [HDR + BB*CX*PSTR + 256];
__device__ __align__(16) float g_tmp[HDR + BB*CG*PSTR + 256];
__device__ __align__(16) float g_a  [HDR + BB*CG*PSTR + 256];
__device__ __align__(16) float g_xu [HDR + BB*CG*PSTR + 256];
__device__ __align__(16) float g_k  [HDR + BB*KD*PSTR + 256];
__device__ __align__(16) float g_g  [HDR + BB*CG*PSTR + 256];
__device__ __align__(16) float g_o1 [HDR + BB*CG*PSTR + 256];
__device__ float g_stats[4*2*CG];

__global__ void zero_stats_kernel() {
    int i = threadIdx.x + blockIdx.x * blockDim.x;
    if (i < 4*2*CG) g_stats[i] = 0.f;
}
__global__ void dummy_kernel() {}

// =====================================================================
// conv3x3 v7: v5 tiling (4 horiz px x 8 co) + SHFL halo exchange.
// Per warp-ci: 3 LDG.128 (12 wf) + 2 predicated edge LDG + 6 shfl
// + 18 LDS.128 broadcasts for 144 fma2.
// =====================================================================
template<int CIN, bool HAS_BIAS, bool DO_STATS, bool DO_RELU>
__global__ void __launch_bounds__(128, 5) conv3x3_v7(
    const float* __restrict__ in, const float* __restrict__ W,
    const float* __restrict__ bias, float* __restrict__ out,
    float* __restrict__ stats, int Cout)
{
    const int b    = blockIdx.z;
    const int co0  = blockIdx.y * 8;
    const int tid  = threadIdx.x;
    const int lane = tid & 31;
    int j = blockIdx.x * 128 + tid;
    const bool jv = j < JOBS5;
    if (!jv) j = 0;
    const int row = j / NGRP;
    const int k4  = (j % NGRP) * 4;
    const bool rowstart = (k4 == 0);   // left halo is a zero pad column

    __shared__ __align__(16) ull sw[32*9*4];   // [ci][tap][copair] = 9 KB

    ull acc[16];   // [px(4)][copair(4)]
    #pragma unroll
    for (int i = 0; i < 16; i++) acc[i] = 0ull;

    const float* inb = in + HDR + (size_t)b*CIN*PSTR + row*PP + k4;

    for (int cc = 0; cc < CIN; cc += 32) {
        __syncthreads();
        for (int i = tid; i < 8*32*9; i += 128) {
            int t  = i % 9;
            int ci = (i / 9) & 31;
            int co = i / 288;
            ((float*)sw)[(((ci*9 + t)*4 + (co >> 1)) << 1) + (co & 1)] =
                W[((size_t)(co0 + co)*CIN + cc + ci)*9 + t];
        }
        __syncthreads();

        #pragma unroll 1
        for (int ci = 0; ci < 32; ci++) {
            const float* pl = inb + (size_t)(cc + ci) * PSTR;
            const ulonglong2* wt = (const ulonglong2*)(sw + ci*36);
            #pragma unroll
            for (int rr = 0; rr < 3; rr++) {
                const float* pr = pl + (rr - 1) * PP;
                float4 v4 = *(const float4*)pr;          // cols k4..k4+3
                // halos via warp shuffle; edges predicated, row start = pad(0)
                float vl = __shfl_up_sync(0xffffffffu,  v4.w, 1);
                float vr = __shfl_down_sync(0xffffffffu, v4.x, 1);
                if (lane == 0)  vl = pr[-1];
                if (lane == 31) vr = pr[4];
                if (rowstart)   vl = 0.f;
                ull iv[6];
                iv[0] = bcast2(vl);  iv[1] = bcast2(v4.x);
                iv[2] = bcast2(v4.y); iv[3] = bcast2(v4.z);
                iv[4] = bcast2(v4.w); iv[5] = bcast2(vr);
                #pragma unroll
                for (int c = 0; c < 3; c++) {
                    ulonglong2 wA = wt[(rr*3 + c)*2 + 0];   // copair 0,1
                    ulonglong2 wB = wt[(rr*3 + c)*2 + 1];   // copair 2,3
                    #pragma unroll
                    for (int px = 0; px < 4; px++) {
                        ull v = iv[px + c];
                        acc[px*4+0] = fma2(wA.x, v, acc[px*4+0]);
                        acc[px*4+1] = fma2(wA.y, v, acc[px*4+1]);
                        acc[px*4+2] = fma2(wB.x, v, acc[px*4+2]);
                        acc[px*4+3] = fma2(wB.y, v, acc[px*4+3]);
                    }
                }
            }
        }
    }

    // -------- epilogue --------
    bool pv[4];
    #pragma unroll
    for (int px = 0; px < 4; px++) pv[px] = jv && (k4 + px) < HY;
    const bool full4 = jv && (k4 + 3) < HY;

    #pragma unroll
    for (int cop = 0; cop < 4; cop++) {
        int coA = co0 + 2*cop, coB = coA + 1;
        float av[4], bv_[4];
        #pragma unroll
        for (int px = 0; px < 4; px++) unpack2(acc[px*4 + cop], av[px], bv_[px]);

        if (DO_STATS) {
            float sA = 0.f, qA = 0.f, sB = 0.f, qB = 0.f;
            #pragma unroll
            for (int px = 0; px < 4; px++) {
                if (pv[px]) {
                    sA += av[px]; qA += av[px]*av[px];
                    sB += bv_[px]; qB += bv_[px]*bv_[px];
                }
            }
            #pragma unroll
            for (int o = 16; o > 0; o >>= 1) {
                sA += __shfl_down_sync(0xffffffffu, sA, o);
                qA += __shfl_down_sync(0xffffffffu, qA, o);
                sB += __shfl_down_sync(0xffffffffu, sB, o);
                qB += __shfl_down_sync(0xffffffffu, qB, o);
            }
            if (lane == 0) {
                atomicAdd(&stats[2*coA],     sA);
                atomicAdd(&stats[2*coA + 1], qA);
                atomicAdd(&stats[2*coB],     sB);
                atomicAdd(&stats[2*coB + 1], qB);
            }
        }

        float bA = HAS_BIAS ? __ldg(bias + coA) : 0.f;
        float bB = HAS_BIAS ? __ldg(bias + coB) : 0.f;
        float oA[4], oB[4];
        #pragma unroll
        for (int px = 0; px < 4; px++) {
            oA[px] = av[px] + bA; oB[px] = bv_[px] + bB;
            if (DO_RELU) { oA[px] = fmaxf(oA[px], 0.f); oB[px] = fmaxf(oB[px], 0.f); }
        }
        size_t pA = HDR + ((size_t)b*Cout + coA)*PSTR + row*PP + k4;
        size_t pB = pA + PSTR;
        if (full4) {
            *(float4*)(out + pA) = make_float4(oA[0], oA[1], oA[2], oA[3]);
            *(float4*)(out + pB) = make_float4(oB[0], oB[1], oB[2], oB[3]);
        } else {
            #pragma unroll
            for (int px = 0; px < 4; px++) {
                if (pv[px]) { out[pA + px] = oA[px]; out[pB + px] = oB[px]; }
            }
        }
    }
}

// =====================================================================
// ConvTranspose: all 4 parity classes in ONE kernel (z = b*4 + class).
// 128-thread blocks. Writes PADDED g_h.
// =====================================================================
template<int NTH, int NTW>
__device__ __forceinline__ void convt_body(
    const float* __restrict__ x, const float* __restrict__ Wt,
    const float* __restrict__ bt, ull* swt, int b, int co0, int bx, int tid)
{
    constexpr int NT  = NTH * NTW;
    constexpr int PY  = (NTH == 2) ? 0 : 1;
    constexpr int PXP = (NTW == 2) ? 0 : 1;
    constexpr int CXN = (PXP == 0) ? 33 : 32;
    constexpr int RY  = (PY  == 0) ? 33 : 32;
    constexpr int NPC = RY * CXN;

    if (bx * 128 >= (NPC + 1) / 2) return;

    const int pair = bx * 128 + tid;
    const int p0 = pair*2, p1 = p0 + 1;
    const bool v0 = p0 < NPC, v1 = p1 < NPC;
    const int cr0 = v0 ? p0 / CXN : 0, cc0_ = v0 ? p0 % CXN : 0;
    const int cr1 = v1 ? p1 / CXN : 0, cc1_ = v1 ? p1 % CXN : 0;

    bool ok0[NT], ok1[NT];
    int  io0[NT], io1[NT];
    #pragma unroll
    for (int tt = 0; tt < NT; tt++) {
        int th = tt / NTW, tw = tt % NTW;
        int iy0 = cr0 - th, ix0 = cc0_ - tw;
        ok0[tt] = v0 && iy0 >= 0 && iy0 < HX && ix0 >= 0 && ix0 < HX;
        io0[tt] = iy0 * HX + ix0;
        int iy1 = cr1 - th, ix1 = cc1_ - tw;
        ok1[tt] = v1 && iy1 >= 0 && iy1 < HX && ix1 >= 0 && ix1 < HX;
        io1[tt] = iy1 * HX + ix1;
    }

    ull accA[8], accB[8];
    #pragma unroll
    for (int i = 0; i < 8; i++) { accA[i] = 0ull; accB[i] = 0ull; }

    const float* xb = x + (size_t)b * CX * HX * HX;

    for (int cc = 0; cc < CX; cc += 32) {
        __syncthreads();
        for (int i = tid; i < 16*32*NT; i += 128) {
            int tt = i % NT;
            int ci = (i / NT) & 31;
            int co = i / (NT * 32);
            int th = tt / NTW, tw = tt % NTW;
            int kh = (NTH == 2) ? 2*th : 1;
            int kw = (NTW == 2) ? 2*tw : 1;
            ((float*)swt)[((ci*8 + (co>>1))*NT + tt)*2 + (co&1)] =
                Wt[((size_t)(co0 + co)*CX + cc + ci)*9 + kh*3 + kw];
        }
        __syncthreads();

        #pragma unroll 1
        for (int ci = 0; ci < 32; ci++) {
            const float* pl = xb + (size_t)(cc + ci) * (HX * HX);
            ull in0[NT], in1[NT];
            #pragma unroll
            for (int tt = 0; tt < NT; tt++) {
                float a  = ok0[tt] ? __ldg(pl + io0[tt]) : 0.f;
                float bb = ok1[tt] ? __ldg(pl + io1[tt]) : 0.f;
                in0[tt] = bcast2(a);
                in1[tt] = bcast2(bb);
            }
            const ull* wbase = swt + ci * 8 * NT;
            #pragma unroll
            for (int cop = 0; cop < 8; cop++) {
                ull w[NT];
                if constexpr (NT == 4) {
                    const ulonglong2* q = (const ulonglong2*)(wbase + cop*4);
                    ulonglong2 q0 = q[0], q1 = q[1];
                    w[0] = q0.x; w[1] = q0.y; w[2] = q1.x; w[3] = q1.y;
                } else if constexpr (NT == 2) {
                    ulonglong2 q0 = ((const ulonglong2*)(wbase + cop*2))[0];
                    w[0] = q0.x; w[1] = q0.y;
                } else {
                    w[0] = wbase[cop];
                }
                ull a = accA[cop], bb2 = accB[cop];
                #pragma unroll
                for (int tt = 0; tt < NT; tt++) {
                    a   = fma2(w[tt], in0[tt], a);
                    bb2 = fma2(w[tt], in1[tt], bb2);
                }
                accA[cop] = a; accB[cop] = bb2;
            }
        }
    }

    const int oy0 = 2*cr0 + PY, ox0 = 2*cc0_ + PXP;
    const int oy1 = 2*cr1 + PY, ox1 = 2*cc1_ + PXP;
    #pragma unroll
    for (int cop = 0; cop < 8; cop++) {
        float a0, a1, b0, b1;
        unpack2(accA[cop], a0, a1);
        unpack2(accB[cop], b0, b1);
        int coA = co0 + 2*cop, coB = coA + 1;
        float bA = __ldg(bt + coA), bB = __ldg(bt + coB);
        if (v0) {
            size_t q = HDR + ((size_t)b*CX + coA)*PSTR + oy0*PP + ox0;
            g_h[q]        = fmaxf(a0 + bA, 0.f);
            g_h[q + PSTR] = fmaxf(a1 + bB, 0.f);
        }
        if (v1) {
            size_t q = HDR + ((size_t)b*CX + coA)*PSTR + oy1*PP + ox1;
            g_h[q]        = fmaxf(b0 + bA, 0.f);
            g_h[q + PSTR] = fmaxf(b1 + bB, 0.f);
        }
    }
}

__global__ void __launch_bounds__(128, 5) convt_all(
    const float* __restrict__ x, const float* __restrict__ Wt,
    const float* __restrict__ bt)
{
    __shared__ __align__(16) ull swt[32 * 8 * 4];
    const int b   = blockIdx.z >> 2;
    const int cls = blockIdx.z & 3;
    const int co0 = blockIdx.y * 16;
    const int tid = threadIdx.x;
    const int bx  = blockIdx.x;
    switch (cls) {
        case 0: convt_body<2,2>(x, Wt, bt, swt, b, co0, bx, tid); break;
        case 1: convt_body<2,1>(x, Wt, bt, swt, b, co0, bx, tid); break;
        case 2: convt_body<1,2>(x, Wt, bt, swt, b, co0, bx, tid); break;
        default: convt_body<1,1>(x, Wt, bt, swt, b, co0, bx, tid); break;
    }
}

// ---------------- BN (batch stats) + ReLU, padded-layout aware --------------
__global__ void bn_relu_kernel(const float* __restrict__ t,
                               const float* __restrict__ stats,
                               const float* __restrict__ gamma,
                               const float* __restrict__ beta,
                               float* __restrict__ out, int outPadded) {
    int i = blockIdx.x * blockDim.x + threadIdx.x;
    if (i >= BB*CG*NPIX) return;
    int plane = i / NPIX;
    int pix   = i % NPIX;
    int row = pix / HY, col = pix % HY;
    int c = plane % CG;
    size_t ain = HDR + (size_t)plane*PSTR + row*PP + col;
    float v = t[ain];
    float m   = stats[2*c]   * (1.f/NBHW);
    float var = stats[2*c+1] * (1.f/NBHW) - m*m;
    float sc  = gamma[c] * rsqrtf(fmaxf(var, 0.f) + EPSB);
    float r = fmaxf(sc * (v - m) + beta[c], 0.f);
    if (outPadded) out[ain] = r;
    else           out[i]   = r;
}

// ---------------- fused gate: depthwise Q + softmax over KD keys ------------
__global__ void gate_kernel(const float* __restrict__ y,
                            const float* __restrict__ Wq,
                            const float* __restrict__ bq,
                            const float* __restrict__ Wv,
                            const float* __restrict__ bv) {
    __shared__ float swv[KD], sbv[KD];
    int tid = threadIdx.x;
    if (tid < KD) { swv[tid] = Wv[tid]; sbv[tid] = bv[tid]; }
    __syncthreads();

    int zc = blockIdx.y;
    int c  = zc % CG;
    int b  = zc / CG;
    int pix = blockIdx.x * 256 + tid;
    if (pix >= NPIX) return;
    int oy = pix / HY, ox = pix % HY;

    const float* p = y + ((size_t)b * CG + c) * NPIX;   // unpadded input
    float qv = __ldg(bq + c);
    #pragma unroll
    for (int ky = 0; ky < 3; ky++) {
        int iy = oy + ky - 1;
        if (iy < 0 || iy >= HY) continue;
        #pragma unroll
        for (int kx = 0; kx < 3; kx++) {
            int ix = ox + kx - 1;
            if (ix < 0 || ix >= HY) continue;
            qv += __ldg(p + iy * HY + ix) * __ldg(Wq + c * 9 + ky * 3 + kx);
        }
    }
    qv = fmaxf(qv, 0.f);

    float yv = __ldg(p + pix);
    const float* kp = g_k + HDR + (size_t)b * KD * PSTR + oy*PP + ox;

    float s[KD];
    float mx = -1e30f;
    #pragma unroll
    for (int d = 0; d < KD; d++) {
        s[d] = qv * __ldg(kp + (size_t)d * PSTR);
        mx = fmaxf(mx, s[d]);
    }
    float se = 0.f, num = 0.f;
    #pragma unroll
    for (int d = 0; d < KD; d++) {
        float e = expf(s[d] - mx);
        se  += e;
        num += e * fmaxf(yv * swv[d] + sbv[d], 0.f);
    }
    g_g[HDR + ((size_t)b * CG + c) * PSTR + oy*PP + ox] = num / se;
}

// ---------------- host launch -----------------------------------------------
extern "C" void kernel_launch(void* const* d_in, const int* in_sizes, int n_in,
                              void* d_out, int out_size) {
    const float* x  = (const float*)d_in[0];
    const float* y  = (const float*)d_in[1];
    const float* Wt = (const float*)d_in[2];
    const float* bt = (const float*)d_in[3];
    const float* W1 = (const float*)d_in[4];
    const float* g1 = (const float*)d_in[5];
    const float* b1 = (const float*)d_in[6];
    const float* W2 = (const float*)d_in[7];
    const float* g2 = (const float*)d_in[8];
    const float* b2 = (const float*)d_in[9];
    const float* Wq = (const float*)d_in[10];
    const float* bq = (const float*)d_in[11];
    const float* Wk = (const float*)d_in[12];
    const float* bk = (const float*)d_in[13];
    const float* Wv = (const float*)d_in[14];
    const float* bv = (const float*)d_in[15];
    const float* W3 = (const float*)d_in[16];
    const float* g3 = (const float*)d_in[17];
    const float* b3 = (const float*)d_in[18];
    const float* W4 = (const float*)d_in[19];
    const float* g4 = (const float*)d_in[20];
    const float* b4 = (const float*)d_in[21];
    float* out = (float*)d_out;

    float *p_h, *p_tmp, *p_a, *p_xu, *p_k, *p_g, *p_o1, *p_stats;
    cudaGetSymbolAddress((void**)&p_h,     g_h);
    cudaGetSymbolAddress((void**)&p_tmp,   g_tmp);
    cudaGetSymbolAddress((void**)&p_a,     g_a);
    cudaGetSymbolAddress((void**)&p_xu,    g_xu);
    cudaGetSymbolAddress((void**)&p_k,     g_k);
    cudaGetSymbolAddress((void**)&p_g,     g_g);
    cudaGetSymbolAddress((void**)&p_o1,    g_o1);
    cudaGetSymbolAddress((void**)&p_stats, g_stats);

    const int BJ = (JOBS5 + 127) / 128;   // 9
    dim3 grdCG(BJ, CG/8, BB);             // 576 blocks of 128 thr
    dim3 grdK (BJ, KD/8, BB);             // 144 blocks
    int  elems = BB * CG * NPIX;
    int  eb = (elems + 255) / 256;

    zero_stats_kernel<<<1, 1024>>>();     // 0
    dummy_kernel<<<1, 32>>>();            // 1
    convt_all<<<dim3(5, CX/16, BB*4), 128>>>(x, Wt, bt);   // 2

    // DoubleConv(256 -> 128)
    conv3x3_v7<CX, false, true, false><<<grdCG, 128>>>(p_h, W1, nullptr, p_tmp, p_stats + 0, CG);    // 3
    bn_relu_kernel<<<eb, 256>>>(p_tmp, p_stats + 0, g1, b1, p_a, 1);                                  // 4
    conv3x3_v7<CG, false, true, false><<<grdCG, 128>>>(p_a, W2, nullptr, p_tmp, p_stats + 2*CG, CG);  // 5
    bn_relu_kernel<<<eb, 256>>>(p_tmp, p_stats + 2*CG, g2, b2, p_xu, 1);

    // Gate: K conv then fused Q+softmax gate
    conv3x3_v7<CG, true, false, true><<<grdK, 128>>>(p_xu, Wk, bk, p_k, nullptr, KD);
    gate_kernel<<<dim3((NPIX + 255)/256, BB*CG), 256>>>(y, Wq, bq, Wv, bv);

    // final DoubleConv(128 -> 128)
    conv3x3_v7<CG, false, true, false><<<grdCG, 128>>>(p_g, W3, nullptr, p_tmp, p_stats + 4*CG, CG);
    bn_relu_kernel<<<eb, 256>>>(p_tmp, p_stats + 4*CG, g3, b3, p_o1, 1);
    conv3x3_v7<CG, false, true, false><<<grdCG, 128>>>(p_o1, W4, nullptr, p_tmp, p_stats + 6*CG, CG);
    bn_relu_kernel<<<eb, 256>>>(p_tmp, p_stats + 6*CG, g4, b4, out, 0);
}

// round 13
// speedup vs baseline: 1.2197x; 1.2197x over previous
#include <cuda_runtime.h>
#include <math.h>

// ---------------- problem constants ----------------
#define BB   4
#define CX   256
#define HX   32
#define HY   65
#define NPIX (HY*HY)   // 4225
#define CG   128
#define KD   32
#define NBHW 16900.0f
#define EPSB 1e-5f

// padded plane layout: pitch 68 floats, 65 data rows + 1 pad row; header in
// front. Pads are NEVER written -> stay .bss zero.
#define PP    68
#define PSTR  (66*PP)     // 4488 floats per plane
#define HDR   (PP + 4)
#define NGRP  17          // col groups of 4 per row
#define JOBS5 (HY*NGRP)   // 1105

typedef unsigned long long ull;

// ---------------- packed f32x2 helpers ----------------
__device__ __forceinline__ ull pack2(float a, float b) {
    ull r; asm("mov.b64 %0, {%1,%2};" : "=l"(r) : "f"(a), "f"(b)); return r;
}
__device__ __forceinline__ ull bcast2(float a) { return pack2(a, a); }
__device__ __forceinline__ void unpack2(ull v, float& a, float& b) {
    asm("mov.b64 {%0,%1}, %2;" : "=f"(a), "=f"(b) : "l"(v));
}
__device__ __forceinline__ ull fma2(ull a, ull b, ull c) {
    ull d; asm("fma.rn.f32x2 %0, %1, %2, %3;" : "=l"(d) : "l"(a), "l"(b), "l"(c)); return d;
}

// ---------------- scratch (zero-initialized .bss; pads stay 0) -----------
__device__ __align__(16) float g_h  [HDR + BB*CX*PSTR + 256];
__device__ __align__(16) float g_tmp[HDR + BB*CG*PSTR + 256];
__device__ __align__(16) float g_a  [HDR + BB*CG*PSTR + 256];
__device__ __align__(16) float g_xu [HDR + BB*CG*PSTR + 256];
__device__ __align__(16) float g_k  [HDR + BB*KD*PSTR + 256];
__device__ __align__(16) float g_g  [HDR + BB*CG*PSTR + 256];
__device__ __align__(16) float g_o1 [HDR + BB*CG*PSTR + 256];
__device__ float g_stats[4*2*CG];

__global__ void zero_stats_kernel() {
    int i = threadIdx.x + blockIdx.x * blockDim.x;
    if (i < 4*2*CG) g_stats[i] = 0.f;
}

// =====================================================================
// conv3x3 v5 (proven, R9/R11): 4 horiz px x 8 co. Used for the K conv.
// =====================================================================
template<int CIN, bool HAS_BIAS, bool DO_STATS, bool DO_RELU>
__global__ void __launch_bounds__(128, 5) conv3x3_v5(
    const float* __restrict__ in, const float* __restrict__ W,
    const float* __restrict__ bias, float* __restrict__ out,
    float* __restrict__ stats, int Cout)
{
    const int b   = blockIdx.z;
    const int co0 = blockIdx.y * 8;
    const int tid = threadIdx.x;
    int j = blockIdx.x * 128 + tid;
    const bool jv = j < JOBS5;
    if (!jv) j = 0;
    const int row = j / NGRP;
    const int k4  = (j % NGRP) * 4;

    __shared__ __align__(16) ull sw[32*9*4];

    ull acc[16];
    #pragma unroll
    for (int i = 0; i < 16; i++) acc[i] = 0ull;

    const float* inb = in + HDR + (size_t)b*CIN*PSTR + row*PP + k4;

    for (int cc = 0; cc < CIN; cc += 32) {
        __syncthreads();
        for (int i = tid; i < 8*32*9; i += 128) {
            int t  = i % 9;
            int ci = (i / 9) & 31;
            int co = i / 288;
            ((float*)sw)[(((ci*9 + t)*4 + (co >> 1)) << 1) + (co & 1)] =
                W[((size_t)(co0 + co)*CIN + cc + ci)*9 + t];
        }
        __syncthreads();

        #pragma unroll 1
        for (int ci = 0; ci < 32; ci++) {
            const float* pl = inb + (size_t)(cc + ci) * PSTR;
            const ulonglong2* wt = (const ulonglong2*)(sw + ci*36);
            #pragma unroll
            for (int rr = 0; rr < 3; rr++) {
                const float* pr = pl + (rr - 1) * PP;
                float4 v4 = *(const float4*)pr;
                float vl = pr[-1], vr = pr[4];
                ull iv[6];
                iv[0] = bcast2(vl);  iv[1] = bcast2(v4.x);
                iv[2] = bcast2(v4.y); iv[3] = bcast2(v4.z);
                iv[4] = bcast2(v4.w); iv[5] = bcast2(vr);
                #pragma unroll
                for (int c = 0; c < 3; c++) {
                    ulonglong2 wA = wt[(rr*3 + c)*2 + 0];
                    ulonglong2 wB = wt[(rr*3 + c)*2 + 1];
                    #pragma unroll
                    for (int px = 0; px < 4; px++) {
                        ull v = iv[px + c];
                        acc[px*4+0] = fma2(wA.x, v, acc[px*4+0]);
                        acc[px*4+1] = fma2(wA.y, v, acc[px*4+1]);
                        acc[px*4+2] = fma2(wB.x, v, acc[px*4+2]);
                        acc[px*4+3] = fma2(wB.y, v, acc[px*4+3]);
                    }
                }
            }
        }
    }

    bool pv[4];
    #pragma unroll
    for (int px = 0; px < 4; px++) pv[px] = jv && (k4 + px) < HY;
    const bool full4 = jv && (k4 + 3) < HY;

    #pragma unroll
    for (int cop = 0; cop < 4; cop++) {
        int coA = co0 + 2*cop, coB = coA + 1;
        float av[4], bv_[4];
        #pragma unroll
        for (int px = 0; px < 4; px++) unpack2(acc[px*4 + cop], av[px], bv_[px]);

        if (DO_STATS) {
            float sA = 0.f, qA = 0.f, sB = 0.f, qB = 0.f;
            #pragma unroll
            for (int px = 0; px < 4; px++) {
                if (pv[px]) {
                    sA += av[px]; qA += av[px]*av[px];
                    sB += bv_[px]; qB += bv_[px]*bv_[px];
                }
            }
            #pragma unroll
            for (int o = 16; o > 0; o >>= 1) {
                sA += __shfl_down_sync(0xffffffffu, sA, o);
                qA += __shfl_down_sync(0xffffffffu, qA, o);
                sB += __shfl_down_sync(0xffffffffu, sB, o);
                qB += __shfl_down_sync(0xffffffffu, qB, o);
            }
            if ((tid & 31) == 0) {
                atomicAdd(&stats[2*coA],     sA);
                atomicAdd(&stats[2*coA + 1], qA);
                atomicAdd(&stats[2*coB],     sB);
                atomicAdd(&stats[2*coB + 1], qB);
            }
        }

        float bA = HAS_BIAS ? __ldg(bias + coA) : 0.f;
        float bB = HAS_BIAS ? __ldg(bias + coB) : 0.f;
        float oA[4], oB[4];
        #pragma unroll
        for (int px = 0; px < 4; px++) {
            oA[px] = av[px] + bA; oB[px] = bv_[px] + bB;
            if (DO_RELU) { oA[px] = fmaxf(oA[px], 0.f); oB[px] = fmaxf(oB[px], 0.f); }
        }
        size_t pA = HDR + ((size_t)b*Cout + coA)*PSTR + row*PP + k4;
        size_t pB = pA + PSTR;
        if (full4) {
            *(float4*)(out + pA) = make_float4(oA[0], oA[1], oA[2], oA[3]);
            *(float4*)(out + pB) = make_float4(oB[0], oB[1], oB[2], oB[3]);
        } else {
            #pragma unroll
            for (int px = 0; px < 4; px++) {
                if (pv[px]) { out[pA + px] = oA[px]; out[pB + px] = oB[px]; }
            }
        }
    }
}

// =====================================================================
// conv3x3 v5s: SPLIT-K(2) variant. CINH = channels per half.
// blockIdx.z = b*2 + half. half 0 -> out0, half 1 -> out1 (partials, no
// bias/relu/stats). Input has 2*CINH channels per batch.
// =====================================================================
template<int CINH>
__global__ void __launch_bounds__(128, 5) conv3x3_v5s(
    const float* __restrict__ in, const float* __restrict__ W,
    float* __restrict__ out0, float* __restrict__ out1, int Cout)
{
    const int b    = blockIdx.z >> 1;
    const int half = blockIdx.z & 1;
    const int co0  = blockIdx.y * 8;
    const int tid  = threadIdx.x;
    float* out = half ? out1 : out0;

    int j = blockIdx.x * 128 + tid;
    const bool jv = j < JOBS5;
    if (!jv) j = 0;
    const int row = j / NGRP;
    const int k4  = (j % NGRP) * 4;

    __shared__ __align__(16) ull sw[32*9*4];

    ull acc[16];
    #pragma unroll
    for (int i = 0; i < 16; i++) acc[i] = 0ull;

    const float* inb = in + HDR
        + ((size_t)b*(2*CINH) + (size_t)half*CINH)*PSTR + row*PP + k4;

    for (int cc = 0; cc < CINH; cc += 32) {
        __syncthreads();
        for (int i = tid; i < 8*32*9; i += 128) {
            int t  = i % 9;
            int ci = (i / 9) & 31;
            int co = i / 288;
            ((float*)sw)[(((ci*9 + t)*4 + (co >> 1)) << 1) + (co & 1)] =
                W[((size_t)(co0 + co)*(2*CINH) + half*CINH + cc + ci)*9 + t];
        }
        __syncthreads();

        #pragma unroll 1
        for (int ci = 0; ci < 32; ci++) {
            const float* pl = inb + (size_t)(cc + ci) * PSTR;
            const ulonglong2* wt = (const ulonglong2*)(sw + ci*36);
            #pragma unroll
            for (int rr = 0; rr < 3; rr++) {
                const float* pr = pl + (rr - 1) * PP;
                float4 v4 = *(const float4*)pr;
                float vl = pr[-1], vr = pr[4];
                ull iv[6];
                iv[0] = bcast2(vl);  iv[1] = bcast2(v4.x);
                iv[2] = bcast2(v4.y); iv[3] = bcast2(v4.z);
                iv[4] = bcast2(v4.w); iv[5] = bcast2(vr);
                #pragma unroll
                for (int c = 0; c < 3; c++) {
                    ulonglong2 wA = wt[(rr*3 + c)*2 + 0];
                    ulonglong2 wB = wt[(rr*3 + c)*2 + 1];
                    #pragma unroll
                    for (int px = 0; px < 4; px++) {
                        ull v = iv[px + c];
                        acc[px*4+0] = fma2(wA.x, v, acc[px*4+0]);
                        acc[px*4+1] = fma2(wA.y, v, acc[px*4+1]);
                        acc[px*4+2] = fma2(wB.x, v, acc[px*4+2]);
                        acc[px*4+3] = fma2(wB.y, v, acc[px*4+3]);
                    }
                }
            }
        }
    }

    bool pv[4];
    #pragma unroll
    for (int px = 0; px < 4; px++) pv[px] = jv && (k4 + px) < HY;
    const bool full4 = jv && (k4 + 3) < HY;

    #pragma unroll
    for (int cop = 0; cop < 4; cop++) {
        int coA = co0 + 2*cop, coB = coA + 1;
        float av[4], bv_[4];
        #pragma unroll
        for (int px = 0; px < 4; px++) unpack2(acc[px*4 + cop], av[px], bv_[px]);
        size_t pA = HDR + ((size_t)b*Cout + coA)*PSTR + row*PP + k4;
        size_t pB = pA + PSTR;
        if (full4) {
            *(float4*)(out + pA) = make_float4(av[0], av[1], av[2], av[3]);
            *(float4*)(out + pB) = make_float4(bv_[0], bv_[1], bv_[2], bv_[3]);
        } else {
            #pragma unroll
            for (int px = 0; px < 4; px++) {
                if (pv[px]) { out[pA + px] = av[px]; out[pB + px] = bv_[px]; }
            }
        }
    }
}

// ---------------- sum partials in place + per-channel stats -----------------
// one block per plane (b*CG + c); t0 <- t0 + t1; stats[c] += (sum, sumsq)
__global__ void sum_stats_kernel(float* __restrict__ t0,
                                 const float* __restrict__ t1,
                                 float* __restrict__ stats) {
    int plane = blockIdx.x;
    int c = plane % CG;
    int tid = threadIdx.x;
    size_t base = HDR + (size_t)plane * PSTR;
    float s = 0.f, q = 0.f;
    for (int pix = tid; pix < NPIX; pix += 256) {
        int row = pix / HY, col = pix % HY;
        size_t a = base + row * PP + col;
        float v = t0[a] + t1[a];
        t0[a] = v;
        s += v; q += v * v;
    }
    __shared__ float rs[256], rq[256];
    rs[tid] = s; rq[tid] = q;
    __syncthreads();
    #pragma unroll
    for (int o = 128; o > 0; o >>= 1) {
        if (tid < o) { rs[tid] += rs[tid + o]; rq[tid] += rq[tid + o]; }
        __syncthreads();
    }
    if (tid == 0) {
        atomicAdd(&stats[2*c],     rs[0]);
        atomicAdd(&stats[2*c + 1], rq[0]);
    }
}

// =====================================================================
// ConvTranspose: all 4 parity classes in ONE kernel (z = b*4 + class).
// 128-thread blocks. Writes PADDED g_h.
// =====================================================================
template<int NTH, int NTW>
__device__ __forceinline__ void convt_body(
    const float* __restrict__ x, const float* __restrict__ Wt,
    const float* __restrict__ bt, ull* swt, int b, int co0, int bx, int tid)
{
    constexpr int NT  = NTH * NTW;
    constexpr int PY  = (NTH == 2) ? 0 : 1;
    constexpr int PXP = (NTW == 2) ? 0 : 1;
    constexpr int CXN = (PXP == 0) ? 33 : 32;
    constexpr int RY  = (PY  == 0) ? 33 : 32;
    constexpr int NPC = RY * CXN;

    if (bx * 128 >= (NPC + 1) / 2) return;

    const int pair = bx * 128 + tid;
    const int p0 = pair*2, p1 = p0 + 1;
    const bool v0 = p0 < NPC, v1 = p1 < NPC;
    const int cr0 = v0 ? p0 / CXN : 0, cc0_ = v0 ? p0 % CXN : 0;
    const int cr1 = v1 ? p1 / CXN : 0, cc1_ = v1 ? p1 % CXN : 0;

    bool ok0[NT], ok1[NT];
    int  io0[NT], io1[NT];
    #pragma unroll
    for (int tt = 0; tt < NT; tt++) {
        int th = tt / NTW, tw = tt % NTW;
        int iy0 = cr0 - th, ix0 = cc0_ - tw;
        ok0[tt] = v0 && iy0 >= 0 && iy0 < HX && ix0 >= 0 && ix0 < HX;
        io0[tt] = iy0 * HX + ix0;
        int iy1 = cr1 - th, ix1 = cc1_ - tw;
        ok1[tt] = v1 && iy1 >= 0 && iy1 < HX && ix1 >= 0 && ix1 < HX;
        io1[tt] = iy1 * HX + ix1;
    }

    ull accA[8], accB[8];
    #pragma unroll
    for (int i = 0; i < 8; i++) { accA[i] = 0ull; accB[i] = 0ull; }

    const float* xb = x + (size_t)b * CX * HX * HX;

    for (int cc = 0; cc < CX; cc += 32) {
        __syncthreads();
        for (int i = tid; i < 16*32*NT; i += 128) {
            int tt = i % NT;
            int ci = (i / NT) & 31;
            int co = i / (NT * 32);
            int th = tt / NTW, tw = tt % NTW;
            int kh = (NTH == 2) ? 2*th : 1;
            int kw = (NTW == 2) ? 2*tw : 1;
            ((float*)swt)[((ci*8 + (co>>1))*NT + tt)*2 + (co&1)] =
                Wt[((size_t)(co0 + co)*CX + cc + ci)*9 + kh*3 + kw];
        }
        __syncthreads();

        #pragma unroll 1
        for (int ci = 0; ci < 32; ci++) {
            const float* pl = xb + (size_t)(cc + ci) * (HX * HX);
            ull in0[NT], in1[NT];
            #pragma unroll
            for (int tt = 0; tt < NT; tt++) {
                float a  = ok0[tt] ? __ldg(pl + io0[tt]) : 0.f;
                float bb = ok1[tt] ? __ldg(pl + io1[tt]) : 0.f;
                in0[tt] = bcast2(a);
                in1[tt] = bcast2(bb);
            }
            const ull* wbase = swt + ci * 8 * NT;
            #pragma unroll
            for (int cop = 0; cop < 8; cop++) {
                ull w[NT];
                if constexpr (NT == 4) {
                    const ulonglong2* q = (const ulonglong2*)(wbase + cop*4);
                    ulonglong2 q0 = q[0], q1 = q[1];
                    w[0] = q0.x; w[1] = q0.y; w[2] = q1.x; w[3] = q1.y;
                } else if constexpr (NT == 2) {
                    ulonglong2 q0 = ((const ulonglong2*)(wbase + cop*2))[0];
                    w[0] = q0.x; w[1] = q0.y;
                } else {
                    w[0] = wbase[cop];
                }
                ull a = accA[cop], bb2 = accB[cop];
                #pragma unroll
                for (int tt = 0; tt < NT; tt++) {
                    a   = fma2(w[tt], in0[tt], a);
                    bb2 = fma2(w[tt], in1[tt], bb2);
                }
                accA[cop] = a; accB[cop] = bb2;
            }
        }
    }

    const int oy0 = 2*cr0 + PY, ox0 = 2*cc0_ + PXP;
    const int oy1 = 2*cr1 + PY, ox1 = 2*cc1_ + PXP;
    #pragma unroll
    for (int cop = 0; cop < 8; cop++) {
        float a0, a1, b0, b1;
        unpack2(accA[cop], a0, a1);
        unpack2(accB[cop], b0, b1);
        int coA = co0 + 2*cop, coB = coA + 1;
        float bA = __ldg(bt + coA), bB = __ldg(bt + coB);
        if (v0) {
            size_t q = HDR + ((size_t)b*CX + coA)*PSTR + oy0*PP + ox0;
            g_h[q]        = fmaxf(a0 + bA, 0.f);
            g_h[q + PSTR] = fmaxf(a1 + bB, 0.f);
        }
        if (v1) {
            size_t q = HDR + ((size_t)b*CX + coA)*PSTR + oy1*PP + ox1;
            g_h[q]        = fmaxf(b0 + bA, 0.f);
            g_h[q + PSTR] = fmaxf(b1 + bB, 0.f);
        }
    }
}

__global__ void __launch_bounds__(128, 5) convt_all(
    const float* __restrict__ x, const float* __restrict__ Wt,
    const float* __restrict__ bt)
{
    __shared__ __align__(16) ull swt[32 * 8 * 4];
    const int b   = blockIdx.z >> 2;
    const int cls = blockIdx.z & 3;
    const int co0 = blockIdx.y * 16;
    const int tid = threadIdx.x;
    const int bx  = blockIdx.x;
    switch (cls) {
        case 0: convt_body<2,2>(x, Wt, bt, swt, b, co0, bx, tid); break;
        case 1: convt_body<2,1>(x, Wt, bt, swt, b, co0, bx, tid); break;
        case 2: convt_body<1,2>(x, Wt, bt, swt, b, co0, bx, tid); break;
        default: convt_body<1,1>(x, Wt, bt, swt, b, co0, bx, tid); break;
    }
}

// ---------------- BN (batch stats) + ReLU, padded-layout aware --------------
__global__ void bn_relu_kernel(const float* __restrict__ t,
                               const float* __restrict__ stats,
                               const float* __restrict__ gamma,
                               const float* __restrict__ beta,
                               float* __restrict__ out, int outPadded) {
    int i = blockIdx.x * blockDim.x + threadIdx.x;
    if (i >= BB*CG*NPIX) return;
    int plane = i / NPIX;
    int pix   = i % NPIX;
    int row = pix / HY, col = pix % HY;
    int c = plane % CG;
    size_t ain = HDR + (size_t)plane*PSTR + row*PP + col;
    float v = t[ain];
    float m   = stats[2*c]   * (1.f/NBHW);
    float var = stats[2*c+1] * (1.f/NBHW) - m*m;
    float sc  = gamma[c] * rsqrtf(fmaxf(var, 0.f) + EPSB);
    float r = fmaxf(sc * (v - m) + beta[c], 0.f);
    if (outPadded) out[ain] = r;
    else           out[i]   = r;
}

// ---------------- fused gate: depthwise Q + softmax over KD keys ------------
__global__ void gate_kernel(const float* __restrict__ y,
                            const float* __restrict__ Wq,
                            const float* __restrict__ bq,
                            const float* __restrict__ Wv,
                            const float* __restrict__ bv) {
    __shared__ float swv[KD], sbv[KD];
    int tid = threadIdx.x;
    if (tid < KD) { swv[tid] = Wv[tid]; sbv[tid] = bv[tid]; }
    __syncthreads();

    int zc = blockIdx.y;
    int c  = zc % CG;
    int b  = zc / CG;
    int pix = blockIdx.x * 256 + tid;
    if (pix >= NPIX) return;
    int oy = pix / HY, ox = pix % HY;

    const float* p = y + ((size_t)b * CG + c) * NPIX;
    float qv = __ldg(bq + c);
    #pragma unroll
    for (int ky = 0; ky < 3; ky++) {
        int iy = oy + ky - 1;
        if (iy < 0 || iy >= HY) continue;
        #pragma unroll
        for (int kx = 0; kx < 3; kx++) {
            int ix = ox + kx - 1;
            if (ix < 0 || ix >= HY) continue;
            qv += __ldg(p + iy * HY + ix) * __ldg(Wq + c * 9 + ky * 3 + kx);
        }
    }
    qv = fmaxf(qv, 0.f);

    float yv = __ldg(p + pix);
    const float* kp = g_k + HDR + (size_t)b * KD * PSTR + oy*PP + ox;

    float s[KD];
    float mx = -1e30f;
    #pragma unroll
    for (int d = 0; d < KD; d++) {
        s[d] = qv * __ldg(kp + (size_t)d * PSTR);
        mx = fmaxf(mx, s[d]);
    }
    float se = 0.f, num = 0.f;
    #pragma unroll
    for (int d = 0; d < KD; d++) {
        float e = expf(s[d] - mx);
        se  += e;
        num += e * fmaxf(yv * swv[d] + sbv[d], 0.f);
    }
    g_g[HDR + ((size_t)b * CG + c) * PSTR + oy*PP + ox] = num / se;
}

// ---------------- host launch -----------------------------------------------
extern "C" void kernel_launch(void* const* d_in, const int* in_sizes, int n_in,
                              void* d_out, int out_size) {
    const float* x  = (const float*)d_in[0];
    const float* y  = (const float*)d_in[1];
    const float* Wt = (const float*)d_in[2];
    const float* bt = (const float*)d_in[3];
    const float* W1 = (const float*)d_in[4];
    const float* g1 = (const float*)d_in[5];
    const float* b1 = (const float*)d_in[6];
    const float* W2 = (const float*)d_in[7];
    const float* g2 = (const float*)d_in[8];
    const float* b2 = (const float*)d_in[9];
    const float* Wq = (const float*)d_in[10];
    const float* bq = (const float*)d_in[11];
    const float* Wk = (const float*)d_in[12];
    const float* bk = (const float*)d_in[13];
    const float* Wv = (const float*)d_in[14];
    const float* bv = (const float*)d_in[15];
    const float* W3 = (const float*)d_in[16];
    const float* g3 = (const float*)d_in[17];
    const float* b3 = (const float*)d_in[18];
    const float* W4 = (const float*)d_in[19];
    const float* g4 = (const float*)d_in[20];
    const float* b4 = (const float*)d_in[21];
    float* out = (float*)d_out;

    float *p_h, *p_tmp, *p_a, *p_xu, *p_k, *p_g, *p_o1, *p_stats;
    cudaGetSymbolAddress((void**)&p_h,     g_h);
    cudaGetSymbolAddress((void**)&p_tmp,   g_tmp);
    cudaGetSymbolAddress((void**)&p_a,     g_a);
    cudaGetSymbolAddress((void**)&p_xu,    g_xu);
    cudaGetSymbolAddress((void**)&p_k,     g_k);
    cudaGetSymbolAddress((void**)&p_g,     g_g);
    cudaGetSymbolAddress((void**)&p_o1,    g_o1);
    cudaGetSymbolAddress((void**)&p_stats, g_stats);

    const int BJ = (JOBS5 + 127) / 128;     // 9
    dim3 grdS (BJ, CG/8, BB*2);             // split-K convs: 1152 blocks
    dim3 grdK (BJ, KD/8, BB);               // K conv: 144 blocks
    int  elems = BB * CG * NPIX;
    int  eb = (elems + 255) / 256;
    int  planes = BB * CG;                  // 512

    zero_stats_kernel<<<1, 1024>>>();                       // 0
    convt_all<<<dim3(5, CX/16, BB*4), 128>>>(x, Wt, bt);    // 1

    // DoubleConv(256 -> 128), split-K
    conv3x3_v5s<128><<<grdS, 128>>>(p_h, W1, p_tmp, p_o1, CG);        // 2
    sum_stats_kernel<<<planes, 256>>>(p_tmp, p_o1, p_stats + 0);      // 3
    bn_relu_kernel<<<eb, 256>>>(p_tmp, p_stats + 0, g1, b1, p_a, 1);  // 4
    conv3x3_v5s<64><<<grdS, 128>>>(p_a, W2, p_tmp, p_o1, CG);         // 5 <- profiled
    sum_stats_kernel<<<planes, 256>>>(p_tmp, p_o1, p_stats + 2*CG);
    bn_relu_kernel<<<eb, 256>>>(p_tmp, p_stats + 2*CG, g2, b2, p_xu, 1);

    // Gate: K conv (unsplit) then fused Q+softmax gate
    conv3x3_v5<CG, true, false, true><<<grdK, 128>>>(p_xu, Wk, bk, p_k, nullptr, KD);
    gate_kernel<<<dim3((NPIX + 255)/256, BB*CG), 256>>>(y, Wq, bq, Wv, bv);

    // final DoubleConv(128 -> 128), split-K
    conv3x3_v5s<64><<<grdS, 128>>>(p_g, W3, p_tmp, p_o1, CG);
    sum_stats_kernel<<<planes, 256>>>(p_tmp, p_o1, p_stats + 4*CG);
    bn_relu_kernel<<<eb, 256>>>(p_tmp, p_stats + 4*CG, g3, b3, p_o1, 1);
    conv3x3_v5s<64><<<grdS, 128>>>(p_o1, W4, p_tmp, p_h, CG);
    sum_stats_kernel<<<planes, 256>>>(p_tmp, p_h, p_stats + 6*CG);
    bn_relu_kernel<<<eb, 256>>>(p_tmp, p_stats + 6*CG, g4, b4, out, 0);
}

// round 14
// speedup vs baseline: 1.2869x; 1.0551x over previous
#include <cuda_runtime.h>
#include <math.h>

// ---------------- problem constants ----------------
#define BB   4
#define CX   256
#define HX   32
#define HY   65
#define NPIX (HY*HY)   // 4225
#define CG   128
#define KD   32
#define NBHW 16900.0f
#define EPSB 1e-5f

// padded plane layout: pitch 68 floats, 65 data rows + 1 pad row; header in
// front. Pads stay zero (either never written, or explicitly re-zeroed).
#define PP    68
#define PROWS 66
#define PSTR  (PROWS*PP)  // 4488 floats per plane
#define HDR   (PP + 4)
#define NGRP  17          // col groups of 4 per row
#define JOBS5 (HY*NGRP)   // 1105
#define CHUNKS (PROWS*NGRP) // 1122 float4 chunks per plane

typedef unsigned long long ull;

// ---------------- packed f32x2 helpers ----------------
__device__ __forceinline__ ull pack2(float a, float b) {
    ull r; asm("mov.b64 %0, {%1,%2};" : "=l"(r) : "f"(a), "f"(b)); return r;
}
__device__ __forceinline__ ull bcast2(float a) { return pack2(a, a); }
__device__ __forceinline__ void unpack2(ull v, float& a, float& b) {
    asm("mov.b64 {%0,%1}, %2;" : "=f"(a), "=f"(b) : "l"(v));
}
__device__ __forceinline__ ull fma2(ull a, ull b, ull c) {
    ull d; asm("fma.rn.f32x2 %0, %1, %2, %3;" : "=l"(d) : "l"(a), "l"(b), "l"(c)); return d;
}

// ---------------- scratch (zero-initialized .bss) -----------
__device__ __align__(16) float g_h  [HDR + BB*CX*PSTR + 256];
__device__ __align__(16) float g_tmp[HDR + BB*CG*PSTR + 256];
__device__ __align__(16) float g_a  [HDR + BB*CG*PSTR + 256];
__device__ __align__(16) float g_xu [HDR + BB*CG*PSTR + 256];
__device__ __align__(16) float g_k  [HDR + BB*KD*PSTR + 256];
__device__ __align__(16) float g_g  [HDR + BB*CG*PSTR + 256];
__device__ __align__(16) float g_o1 [HDR + BB*CG*PSTR + 256];
__device__ float g_stats[4*2*CG];

__global__ void zero_stats_kernel() {
    int i = threadIdx.x + blockIdx.x * blockDim.x;
    if (i < 4*2*CG) g_stats[i] = 0.f;
}

// =====================================================================
// conv3x3 v5 (proven): 4 horiz px x 8 co, fused stats.
// =====================================================================
template<int CIN, bool HAS_BIAS, bool DO_STATS, bool DO_RELU>
__global__ void __launch_bounds__(128, 5) conv3x3_v5(
    const float* __restrict__ in, const float* __restrict__ W,
    const float* __restrict__ bias, float* __restrict__ out,
    float* __restrict__ stats, int Cout)
{
    const int b   = blockIdx.z;
    const int co0 = blockIdx.y * 8;
    const int tid = threadIdx.x;
    int j = blockIdx.x * 128 + tid;
    const bool jv = j < JOBS5;
    if (!jv) j = 0;
    const int row = j / NGRP;
    const int k4  = (j % NGRP) * 4;

    __shared__ __align__(16) ull sw[32*9*4];

    ull acc[16];
    #pragma unroll
    for (int i = 0; i < 16; i++) acc[i] = 0ull;

    const float* inb = in + HDR + (size_t)b*CIN*PSTR + row*PP + k4;

    for (int cc = 0; cc < CIN; cc += 32) {
        __syncthreads();
        for (int i = tid; i < 8*32*9; i += 128) {
            int t  = i % 9;
            int ci = (i / 9) & 31;
            int co = i / 288;
            ((float*)sw)[(((ci*9 + t)*4 + (co >> 1)) << 1) + (co & 1)] =
                W[((size_t)(co0 + co)*CIN + cc + ci)*9 + t];
        }
        __syncthreads();

        #pragma unroll 1
        for (int ci = 0; ci < 32; ci++) {
            const float* pl = inb + (size_t)(cc + ci) * PSTR;
            const ulonglong2* wt = (const ulonglong2*)(sw + ci*36);
            #pragma unroll
            for (int rr = 0; rr < 3; rr++) {
                const float* pr = pl + (rr - 1) * PP;
                float4 v4 = *(const float4*)pr;
                float vl = pr[-1], vr = pr[4];
                ull iv[6];
                iv[0] = bcast2(vl);  iv[1] = bcast2(v4.x);
                iv[2] = bcast2(v4.y); iv[3] = bcast2(v4.z);
                iv[4] = bcast2(v4.w); iv[5] = bcast2(vr);
                #pragma unroll
                for (int c = 0; c < 3; c++) {
                    ulonglong2 wA = wt[(rr*3 + c)*2 + 0];
                    ulonglong2 wB = wt[(rr*3 + c)*2 + 1];
                    #pragma unroll
                    for (int px = 0; px < 4; px++) {
                        ull v = iv[px + c];
                        acc[px*4+0] = fma2(wA.x, v, acc[px*4+0]);
                        acc[px*4+1] = fma2(wA.y, v, acc[px*4+1]);
                        acc[px*4+2] = fma2(wB.x, v, acc[px*4+2]);
                        acc[px*4+3] = fma2(wB.y, v, acc[px*4+3]);
                    }
                }
            }
        }
    }

    bool pv[4];
    #pragma unroll
    for (int px = 0; px < 4; px++) pv[px] = jv && (k4 + px) < HY;
    const bool full4 = jv && (k4 + 3) < HY;

    #pragma unroll
    for (int cop = 0; cop < 4; cop++) {
        int coA = co0 + 2*cop, coB = coA + 1;
        float av[4], bv_[4];
        #pragma unroll
        for (int px = 0; px < 4; px++) unpack2(acc[px*4 + cop], av[px], bv_[px]);

        if (DO_STATS) {
            float sA = 0.f, qA = 0.f, sB = 0.f, qB = 0.f;
            #pragma unroll
            for (int px = 0; px < 4; px++) {
                if (pv[px]) {
                    sA += av[px]; qA += av[px]*av[px];
                    sB += bv_[px]; qB += bv_[px]*bv_[px];
                }
            }
            #pragma unroll
            for (int o = 16; o > 0; o >>= 1) {
                sA += __shfl_down_sync(0xffffffffu, sA, o);
                qA += __shfl_down_sync(0xffffffffu, qA, o);
                sB += __shfl_down_sync(0xffffffffu, sB, o);
                qB += __shfl_down_sync(0xffffffffu, qB, o);
            }
            if ((tid & 31) == 0) {
                atomicAdd(&stats[2*coA],     sA);
                atomicAdd(&stats[2*coA + 1], qA);
                atomicAdd(&stats[2*coB],     sB);
                atomicAdd(&stats[2*coB + 1], qB);
            }
        }

        float bA = HAS_BIAS ? __ldg(bias + coA) : 0.f;
        float bB = HAS_BIAS ? __ldg(bias + coB) : 0.f;
        float oA[4], oB[4];
        #pragma unroll
        for (int px = 0; px < 4; px++) {
            oA[px] = av[px] + bA; oB[px] = bv_[px] + bB;
            if (DO_RELU) { oA[px] = fmaxf(oA[px], 0.f); oB[px] = fmaxf(oB[px], 0.f); }
        }
        size_t pA = HDR + ((size_t)b*Cout + coA)*PSTR + row*PP + k4;
        size_t pB = pA + PSTR;
        if (full4) {
            *(float4*)(out + pA) = make_float4(oA[0], oA[1], oA[2], oA[3]);
            *(float4*)(out + pB) = make_float4(oB[0], oB[1], oB[2], oB[3]);
        } else {
            #pragma unroll
            for (int px = 0; px < 4; px++) {
                if (pv[px]) { out[pA + px] = oA[px]; out[pB + px] = oB[px]; }
            }
        }
    }
}

// =====================================================================
// conv3x3 v5s: SPLIT-K(2) variant for conv1 only (CINH = 128).
// =====================================================================
template<int CINH>
__global__ void __launch_bounds__(128, 5) conv3x3_v5s(
    const float* __restrict__ in, const float* __restrict__ W,
    float* __restrict__ out0, float* __restrict__ out1, int Cout)
{
    const int b    = blockIdx.z >> 1;
    const int half = blockIdx.z & 1;
    const int co0  = blockIdx.y * 8;
    const int tid  = threadIdx.x;
    float* out = half ? out1 : out0;

    int j = blockIdx.x * 128 + tid;
    const bool jv = j < JOBS5;
    if (!jv) j = 0;
    const int row = j / NGRP;
    const int k4  = (j % NGRP) * 4;

    __shared__ __align__(16) ull sw[32*9*4];

    ull acc[16];
    #pragma unroll
    for (int i = 0; i < 16; i++) acc[i] = 0ull;

    const float* inb = in + HDR
        + ((size_t)b*(2*CINH) + (size_t)half*CINH)*PSTR + row*PP + k4;

    for (int cc = 0; cc < CINH; cc += 32) {
        __syncthreads();
        for (int i = tid; i < 8*32*9; i += 128) {
            int t  = i % 9;
            int ci = (i / 9) & 31;
            int co = i / 288;
            ((float*)sw)[(((ci*9 + t)*4 + (co >> 1)) << 1) + (co & 1)] =
                W[((size_t)(co0 + co)*(2*CINH) + half*CINH + cc + ci)*9 + t];
        }
        __syncthreads();

        #pragma unroll 1
        for (int ci = 0; ci < 32; ci++) {
            const float* pl = inb + (size_t)(cc + ci) * PSTR;
            const ulonglong2* wt = (const ulonglong2*)(sw + ci*36);
            #pragma unroll
            for (int rr = 0; rr < 3; rr++) {
                const float* pr = pl + (rr - 1) * PP;
                float4 v4 = *(const float4*)pr;
                float vl = pr[-1], vr = pr[4];
                ull iv[6];
                iv[0] = bcast2(vl);  iv[1] = bcast2(v4.x);
                iv[2] = bcast2(v4.y); iv[3] = bcast2(v4.z);
                iv[4] = bcast2(v4.w); iv[5] = bcast2(vr);
                #pragma unroll
                for (int c = 0; c < 3; c++) {
                    ulonglong2 wA = wt[(rr*3 + c)*2 + 0];
                    ulonglong2 wB = wt[(rr*3 + c)*2 + 1];
                    #pragma unroll
                    for (int px = 0; px < 4; px++) {
                        ull v = iv[px + c];
                        acc[px*4+0] = fma2(wA.x, v, acc[px*4+0]);
                        acc[px*4+1] = fma2(wA.y, v, acc[px*4+1]);
                        acc[px*4+2] = fma2(wB.x, v, acc[px*4+2]);
                        acc[px*4+3] = fma2(wB.y, v, acc[px*4+3]);
                    }
                }
            }
        }
    }

    bool pv[4];
    #pragma unroll
    for (int px = 0; px < 4; px++) pv[px] = jv && (k4 + px) < HY;
    const bool full4 = jv && (k4 + 3) < HY;

    #pragma unroll
    for (int cop = 0; cop < 4; cop++) {
        int coA = co0 + 2*cop, coB = coA + 1;
        float av[4], bv_[4];
        #pragma unroll
        for (int px = 0; px < 4; px++) unpack2(acc[px*4 + cop], av[px], bv_[px]);
        size_t pA = HDR + ((size_t)b*Cout + coA)*PSTR + row*PP + k4;
        size_t pB = pA + PSTR;
        if (full4) {
            *(float4*)(out + pA) = make_float4(av[0], av[1], av[2], av[3]);
            *(float4*)(out + pB) = make_float4(bv_[0], bv_[1], bv_[2], bv_[3]);
        } else {
            #pragma unroll
            for (int px = 0; px < 4; px++) {
                if (pv[px]) { out[pA + px] = av[px]; out[pB + px] = bv_[px]; }
            }
        }
    }
}

// ---------------- sum partials in place + per-channel stats (float4) --------
// Pads are 0 in both buffers: 0+0=0 stored, contributes 0 to sum/sumsq.
__global__ void sum_stats_v2(float* __restrict__ t0,
                             const float* __restrict__ t1,
                             float* __restrict__ stats) {
    int plane = blockIdx.x;
    int c = plane % CG;
    int tid = threadIdx.x;
    size_t base = HDR + (size_t)plane * PSTR;
    float s = 0.f, q = 0.f;
    for (int ch = tid; ch < CHUNKS; ch += 256) {
        size_t a = base + ch * 4;
        float4 v0 = *(const float4*)(t0 + a);
        float4 v1 = *(const float4*)(t1 + a);
        float4 v = make_float4(v0.x+v1.x, v0.y+v1.y, v0.z+v1.z, v0.w+v1.w);
        *(float4*)(t0 + a) = v;
        s += v.x + v.y + v.z + v.w;
        q += v.x*v.x + v.y*v.y + v.z*v.z + v.w*v.w;
    }
    #pragma unroll
    for (int o = 16; o > 0; o >>= 1) {
        s += __shfl_down_sync(0xffffffffu, s, o);
        q += __shfl_down_sync(0xffffffffu, q, o);
    }
    __shared__ float rs[8], rq[8];
    int w = tid >> 5;
    if ((tid & 31) == 0) { rs[w] = s; rq[w] = q; }
    __syncthreads();
    if (tid == 0) {
        float S = 0.f, Q = 0.f;
        #pragma unroll
        for (int i = 0; i < 8; i++) { S += rs[i]; Q += rq[i]; }
        atomicAdd(&stats[2*c],     S);
        atomicAdd(&stats[2*c + 1], Q);
    }
}

// ---------------- BN+ReLU padded->padded, float4, pads forced to 0 ----------
__global__ void bn_relu_pad(const float* __restrict__ t,
                            const float* __restrict__ stats,
                            const float* __restrict__ gamma,
                            const float* __restrict__ beta,
                            float* __restrict__ out) {
    int idx = blockIdx.x * 256 + threadIdx.x;
    if (idx >= BB*CG*CHUNKS) return;
    int plane = idx / CHUNKS;
    int ch    = idx % CHUNKS;
    int row   = ch / NGRP;
    int c4    = (ch % NGRP) * 4;
    int c = plane % CG;
    float m   = stats[2*c]   * (1.f/NBHW);
    float var = stats[2*c+1] * (1.f/NBHW) - m*m;
    float sc  = gamma[c] * rsqrtf(fmaxf(var, 0.f) + EPSB);
    float sh  = beta[c] - sc * m;
    size_t a = HDR + (size_t)plane*PSTR + (size_t)ch*4;
    float4 v = *(const float4*)(t + a);
    float4 o;
    o.x = fmaxf(sc*v.x + sh, 0.f);
    o.y = fmaxf(sc*v.y + sh, 0.f);
    o.z = fmaxf(sc*v.z + sh, 0.f);
    o.w = fmaxf(sc*v.w + sh, 0.f);
    // zero pad lanes (row 65, or cols >= 65)
    if (row >= HY) { o.x = o.y = o.z = o.w = 0.f; }
    else {
        if (c4 + 0 >= HY) o.x = 0.f;
        if (c4 + 1 >= HY) o.y = 0.f;
        if (c4 + 2 >= HY) o.z = 0.f;
        if (c4 + 3 >= HY) o.w = 0.f;
    }
    *(float4*)(out + a) = o;
}

// ---------------- BN+ReLU padded -> flat output ------------------------------
__global__ void bn_relu_out(const float* __restrict__ t,
                            const float* __restrict__ stats,
                            const float* __restrict__ gamma,
                            const float* __restrict__ beta,
                            float* __restrict__ out) {
    int i = blockIdx.x * blockDim.x + threadIdx.x;
    if (i >= BB*CG*NPIX) return;
    int plane = i / NPIX;
    int pix   = i % NPIX;
    int row = pix / HY, col = pix % HY;
    int c = plane % CG;
    size_t ain = HDR + (size_t)plane*PSTR + row*PP + col;
    float v = t[ain];
    float m   = stats[2*c]   * (1.f/NBHW);
    float var = stats[2*c+1] * (1.f/NBHW) - m*m;
    float sc  = gamma[c] * rsqrtf(fmaxf(var, 0.f) + EPSB);
    out[i] = fmaxf(sc * (v - m) + beta[c], 0.f);
}

// =====================================================================
// ConvTranspose: all 4 parity classes in ONE kernel (z = b*4 + class).
// =====================================================================
template<int NTH, int NTW>
__device__ __forceinline__ void convt_body(
    const float* __restrict__ x, const float* __restrict__ Wt,
    const float* __restrict__ bt, ull* swt, int b, int co0, int bx, int tid)
{
    constexpr int NT  = NTH * NTW;
    constexpr int PY  = (NTH == 2) ? 0 : 1;
    constexpr int PXP = (NTW == 2) ? 0 : 1;
    constexpr int CXN = (PXP == 0) ? 33 : 32;
    constexpr int RY  = (PY  == 0) ? 33 : 32;
    constexpr int NPC = RY * CXN;

    if (bx * 128 >= (NPC + 1) / 2) return;

    const int pair = bx * 128 + tid;
    const int p0 = pair*2, p1 = p0 + 1;
    const bool v0 = p0 < NPC, v1 = p1 < NPC;
    const int cr0 = v0 ? p0 / CXN : 0, cc0_ = v0 ? p0 % CXN : 0;
    const int cr1 = v1 ? p1 / CXN : 0, cc1_ = v1 ? p1 % CXN : 0;

    bool ok0[NT], ok1[NT];
    int  io0[NT], io1[NT];
    #pragma unroll
    for (int tt = 0; tt < NT; tt++) {
        int th = tt / NTW, tw = tt % NTW;
        int iy0 = cr0 - th, ix0 = cc0_ - tw;
        ok0[tt] = v0 && iy0 >= 0 && iy0 < HX && ix0 >= 0 && ix0 < HX;
        io0[tt] = iy0 * HX + ix0;
        int iy1 = cr1 - th, ix1 = cc1_ - tw;
        ok1[tt] = v1 && iy1 >= 0 && iy1 < HX && ix1 >= 0 && ix1 < HX;
        io1[tt] = iy1 * HX + ix1;
    }

    ull accA[8], accB[8];
    #pragma unroll
    for (int i = 0; i < 8; i++) { accA[i] = 0ull; accB[i] = 0ull; }

    const float* xb = x + (size_t)b * CX * HX * HX;

    for (int cc = 0; cc < CX; cc += 32) {
        __syncthreads();
        for (int i = tid; i < 16*32*NT; i += 128) {
            int tt = i % NT;
            int ci = (i / NT) & 31;
            int co = i / (NT * 32);
            int th = tt / NTW, tw = tt % NTW;
            int kh = (NTH == 2) ? 2*th : 1;
            int kw = (NTW == 2) ? 2*tw : 1;
            ((float*)swt)[((ci*8 + (co>>1))*NT + tt)*2 + (co&1)] =
                Wt[((size_t)(co0 + co)*CX + cc + ci)*9 + kh*3 + kw];
        }
        __syncthreads();

        #pragma unroll 1
        for (int ci = 0; ci < 32; ci++) {
            const float* pl = xb + (size_t)(cc + ci) * (HX * HX);
            ull in0[NT], in1[NT];
            #pragma unroll
            for (int tt = 0; tt < NT; tt++) {
                float a  = ok0[tt] ? __ldg(pl + io0[tt]) : 0.f;
                float bb = ok1[tt] ? __ldg(pl + io1[tt]) : 0.f;
                in0[tt] = bcast2(a);
                in1[tt] = bcast2(bb);
            }
            const ull* wbase = swt + ci * 8 * NT;
            #pragma unroll
            for (int cop = 0; cop < 8; cop++) {
                ull w[NT];
                if constexpr (NT == 4) {
                    const ulonglong2* q = (const ulonglong2*)(wbase + cop*4);
                    ulonglong2 q0 = q[0], q1 = q[1];
                    w[0] = q0.x; w[1] = q0.y; w[2] = q1.x; w[3] = q1.y;
                } else if constexpr (NT == 2) {
                    ulonglong2 q0 = ((const ulonglong2*)(wbase + cop*2))[0];
                    w[0] = q0.x; w[1] = q0.y;
                } else {
                    w[0] = wbase[cop];
                }
                ull a = accA[cop], bb2 = accB[cop];
                #pragma unroll
                for (int tt = 0; tt < NT; tt++) {
                    a   = fma2(w[tt], in0[tt], a);
                    bb2 = fma2(w[tt], in1[tt], bb2);
                }
                accA[cop] = a; accB[cop] = bb2;
            }
        }
    }

    const int oy0 = 2*cr0 + PY, ox0 = 2*cc0_ + PXP;
    const int oy1 = 2*cr1 + PY, ox1 = 2*cc1_ + PXP;
    #pragma unroll
    for (int cop = 0; cop < 8; cop++) {
        float a0, a1, b0, b1;
        unpack2(accA[cop], a0, a1);
        unpack2(accB[cop], b0, b1);
        int coA = co0 + 2*cop, coB = coA + 1;
        float bA = __ldg(bt + coA), bB = __ldg(bt + coB);
        if (v0) {
            size_t q = HDR + ((size_t)b*CX + coA)*PSTR + oy0*PP + ox0;
            g_h[q]        = fmaxf(a0 + bA, 0.f);
            g_h[q + PSTR] = fmaxf(a1 + bB, 0.f);
        }
        if (v1) {
            size_t q = HDR + ((size_t)b*CX + coA)*PSTR + oy1*PP + ox1;
            g_h[q]        = fmaxf(b0 + bA, 0.f);
            g_h[q + PSTR] = fmaxf(b1 + bB, 0.f);
        }
    }
}

__global__ void __launch_bounds__(128, 5) convt_all(
    const float* __restrict__ x, const float* __restrict__ Wt,
    const float* __restrict__ bt)
{
    __shared__ __align__(16) ull swt[32 * 8 * 4];
    const int b   = blockIdx.z >> 2;
    const int cls = blockIdx.z & 3;
    const int co0 = blockIdx.y * 16;
    const int tid = threadIdx.x;
    const int bx  = blockIdx.x;
    switch (cls) {
        case 0: convt_body<2,2>(x, Wt, bt, swt, b, co0, bx, tid); break;
        case 1: convt_body<2,1>(x, Wt, bt, swt, b, co0, bx, tid); break;
        case 2: convt_body<1,2>(x, Wt, bt, swt, b, co0, bx, tid); break;
        default: convt_body<1,1>(x, Wt, bt, swt, b, co0, bx, tid); break;
    }
}

// ---------------- fused gate: depthwise Q + softmax over KD keys ------------
__global__ void gate_kernel(const float* __restrict__ y,
                            const float* __restrict__ Wq,
                            const float* __restrict__ bq,
                            const float* __restrict__ Wv,
                            const float* __restrict__ bv) {
    __shared__ float swv[KD], sbv[KD];
    int tid = threadIdx.x;
    if (tid < KD) { swv[tid] = Wv[tid]; sbv[tid] = bv[tid]; }
    __syncthreads();

    int zc = blockIdx.y;
    int c  = zc % CG;
    int b  = zc / CG;
    int pix = blockIdx.x * 256 + tid;
    if (pix >= NPIX) return;
    int oy = pix / HY, ox = pix % HY;

    const float* p = y + ((size_t)b * CG + c) * NPIX;
    float qv = __ldg(bq + c);
    #pragma unroll
    for (int ky = 0; ky < 3; ky++) {
        int iy = oy + ky - 1;
        if (iy < 0 || iy >= HY) continue;
        #pragma unroll
        for (int kx = 0; kx < 3; kx++) {
            int ix = ox + kx - 1;
            if (ix < 0 || ix >= HY) continue;
            qv += __ldg(p + iy * HY + ix) * __ldg(Wq + c * 9 + ky * 3 + kx);
        }
    }
    qv = fmaxf(qv, 0.f);

    float yv = __ldg(p + pix);
    const float* kp = g_k + HDR + (size_t)b * KD * PSTR + oy*PP + ox;

    float s[KD];
    float mx = -1e30f;
    #pragma unroll
    for (int d = 0; d < KD; d++) {
        s[d] = qv * __ldg(kp + (size_t)d * PSTR);
        mx = fmaxf(mx, s[d]);
    }
    float se = 0.f, num = 0.f;
    #pragma unroll
    for (int d = 0; d < KD; d++) {
        float e = expf(s[d] - mx);
        se  += e;
        num += e * fmaxf(yv * swv[d] + sbv[d], 0.f);
    }
    g_g[HDR + ((size_t)b * CG + c) * PSTR + oy*PP + ox] = num / se;
}

// ---------------- host launch -----------------------------------------------
extern "C" void kernel_launch(void* const* d_in, const int* in_sizes, int n_in,
                              void* d_out, int out_size) {
    const float* x  = (const float*)d_in[0];
    const float* y  = (const float*)d_in[1];
    const float* Wt = (const float*)d_in[2];
    const float* bt = (const float*)d_in[3];
    const float* W1 = (const float*)d_in[4];
    const float* g1 = (const float*)d_in[5];
    const float* b1 = (const float*)d_in[6];
    const float* W2 = (const float*)d_in[7];
    const float* g2 = (const float*)d_in[8];
    const float* b2 = (const float*)d_in[9];
    const float* Wq = (const float*)d_in[10];
    const float* bq = (const float*)d_in[11];
    const float* Wk = (const float*)d_in[12];
    const float* bk = (const float*)d_in[13];
    const float* Wv = (const float*)d_in[14];
    const float* bv = (const float*)d_in[15];
    const float* W3 = (const float*)d_in[16];
    const float* g3 = (const float*)d_in[17];
    const float* b3 = (const float*)d_in[18];
    const float* W4 = (const float*)d_in[19];
    const float* g4 = (const float*)d_in[20];
    const float* b4 = (const float*)d_in[21];
    float* out = (float*)d_out;

    float *p_h, *p_tmp, *p_a, *p_xu, *p_k, *p_g, *p_o1, *p_stats;
    cudaGetSymbolAddress((void**)&p_h,     g_h);
    cudaGetSymbolAddress((void**)&p_tmp,   g_tmp);
    cudaGetSymbolAddress((void**)&p_a,     g_a);
    cudaGetSymbolAddress((void**)&p_xu,    g_xu);
    cudaGetSymbolAddress((void**)&p_k,     g_k);
    cudaGetSymbolAddress((void**)&p_g,     g_g);
    cudaGetSymbolAddress((void**)&p_o1,    g_o1);
    cudaGetSymbolAddress((void**)&p_stats, g_stats);

    const int BJ = (JOBS5 + 127) / 128;     // 9
    dim3 grdS (BJ, CG/8, BB*2);             // split conv1: 1152 blocks
    dim3 grdCG(BJ, CG/8, BB);               // unsplit CG convs: 576 blocks
    dim3 grdK (BJ, KD/8, BB);               // K conv: 144 blocks
    int  elems  = BB * CG * NPIX;
    int  eb     = (elems + 255) / 256;
    int  planes = BB * CG;                  // 512
    int  padBlocks = (planes * CHUNKS + 255) / 256;   // bn_relu_pad grid

    zero_stats_kernel<<<1, 1024>>>();
    convt_all<<<dim3(5, CX/16, BB*4), 128>>>(x, Wt, bt);

    // conv1 (256 -> 128): split-K(2)
    conv3x3_v5s<128><<<grdS, 128>>>(p_h, W1, p_tmp, p_o1, CG);
    sum_stats_v2<<<planes, 256>>>(p_tmp, p_o1, p_stats + 0);
    bn_relu_pad<<<padBlocks, 256>>>(p_tmp, p_stats + 0, g1, b1, p_a);

    // conv2 (128 -> 128): unsplit, fused stats
    conv3x3_v5<CG, false, true, false><<<grdCG, 128>>>(p_a, W2, nullptr, p_tmp, p_stats + 2*CG, CG);
    bn_relu_pad<<<padBlocks, 256>>>(p_tmp, p_stats + 2*CG, g2, b2, p_xu);

    // Gate: K conv then fused Q+softmax gate
    conv3x3_v5<CG, true, false, true><<<grdK, 128>>>(p_xu, Wk, bk, p_k, nullptr, KD);
    gate_kernel<<<dim3((NPIX + 255)/256, BB*CG), 256>>>(y, Wq, bq, Wv, bv);

    // final DoubleConv (128 -> 128): unsplit, fused stats
    conv3x3_v5<CG, false, true, false><<<grdCG, 128>>>(p_g, W3, nullptr, p_tmp, p_stats + 4*CG, CG);
    bn_relu_pad<<<padBlocks, 256>>>(p_tmp, p_stats + 4*CG, g3, b3, p_o1);
    conv3x3_v5<CG, false, true, false><<<grdCG, 128>>>(p_o1, W4, nullptr, p_tmp, p_stats + 6*CG, CG);
    bn_relu_out<<<eb, 256>>>(p_tmp, p_stats + 6*CG, g4, b4, out);
}

// round 15
// speedup vs baseline: 1.3062x; 1.0151x over previous
#include <cuda_runtime.h>
#include <math.h>

// ---------------- problem constants ----------------
#define BB   4
#define CX   256
#define HX   32
#define HY   65
#define NPIX (HY*HY)   // 4225
#define CG   128
#define KD   32
#define NBHW 16900.0f
#define EPSB 1e-5f

// padded plane layout: pitch 68 floats, 65 data rows + 1 pad row; header in
// front. Pads stay zero (never written, or explicitly re-zeroed).
#define PP    68
#define PROWS 66
#define PSTR  (PROWS*PP)  // 4488 floats per plane
#define HDR   (PP + 4)
#define NGRP  17          // col groups of 4 per row
#define JOBS5 (HY*NGRP)   // 1105
#define CHUNKS (PROWS*NGRP) // 1122 float4 chunks per plane
#define KSTRIDE ((size_t)BB*KD*PSTR)   // one K-partial buffer

typedef unsigned long long ull;

// ---------------- packed f32x2 helpers ----------------
__device__ __forceinline__ ull pack2(float a, float b) {
    ull r; asm("mov.b64 %0, {%1,%2};" : "=l"(r) : "f"(a), "f"(b)); return r;
}
__device__ __forceinline__ ull bcast2(float a) { return pack2(a, a); }
__device__ __forceinline__ void unpack2(ull v, float& a, float& b) {
    asm("mov.b64 {%0,%1}, %2;" : "=f"(a), "=f"(b) : "l"(v));
}
__device__ __forceinline__ ull fma2(ull a, ull b, ull c) {
    ull d; asm("fma.rn.f32x2 %0, %1, %2, %3;" : "=l"(d) : "l"(a), "l"(b), "l"(c)); return d;
}

// ---------------- scratch (zero-initialized .bss) -----------
__device__ __align__(16) float g_h  [HDR + BB*CX*PSTR + 256];
__device__ __align__(16) float g_tmp[HDR + BB*CG*PSTR + 256];
__device__ __align__(16) float g_a  [HDR + BB*CG*PSTR + 256];
__device__ __align__(16) float g_xu [HDR + BB*CG*PSTR + 256];
__device__ __align__(16) float g_k  [HDR + BB*KD*PSTR + 256];
__device__ __align__(16) float g_g  [HDR + BB*CG*PSTR + 256];
__device__ __align__(16) float g_o1 [HDR + BB*CG*PSTR + 256];
__device__ float g_stats[4*2*CG];

__global__ void zero_stats_kernel() {
    int i = threadIdx.x + blockIdx.x * blockDim.x;
    if (i < 4*2*CG) g_stats[i] = 0.f;
}

// =====================================================================
// conv3x3 v5 (proven): 4 horiz px x 8 co, fused stats.
// =====================================================================
template<int CIN, bool HAS_BIAS, bool DO_STATS, bool DO_RELU>
__global__ void __launch_bounds__(128, 5) conv3x3_v5(
    const float* __restrict__ in, const float* __restrict__ W,
    const float* __restrict__ bias, float* __restrict__ out,
    float* __restrict__ stats, int Cout)
{
    const int b   = blockIdx.z;
    const int co0 = blockIdx.y * 8;
    const int tid = threadIdx.x;
    int j = blockIdx.x * 128 + tid;
    const bool jv = j < JOBS5;
    if (!jv) j = 0;
    const int row = j / NGRP;
    const int k4  = (j % NGRP) * 4;

    __shared__ __align__(16) ull sw[32*9*4];

    ull acc[16];
    #pragma unroll
    for (int i = 0; i < 16; i++) acc[i] = 0ull;

    const float* inb = in + HDR + (size_t)b*CIN*PSTR + row*PP + k4;

    for (int cc = 0; cc < CIN; cc += 32) {
        __syncthreads();
        for (int i = tid; i < 8*32*9; i += 128) {
            int t  = i % 9;
            int ci = (i / 9) & 31;
            int co = i / 288;
            ((float*)sw)[(((ci*9 + t)*4 + (co >> 1)) << 1) + (co & 1)] =
                W[((size_t)(co0 + co)*CIN + cc + ci)*9 + t];
        }
        __syncthreads();

        #pragma unroll 1
        for (int ci = 0; ci < 32; ci++) {
            const float* pl = inb + (size_t)(cc + ci) * PSTR;
            const ulonglong2* wt = (const ulonglong2*)(sw + ci*36);
            #pragma unroll
            for (int rr = 0; rr < 3; rr++) {
                const float* pr = pl + (rr - 1) * PP;
                float4 v4 = *(const float4*)pr;
                float vl = pr[-1], vr = pr[4];
                ull iv[6];
                iv[0] = bcast2(vl);  iv[1] = bcast2(v4.x);
                iv[2] = bcast2(v4.y); iv[3] = bcast2(v4.z);
                iv[4] = bcast2(v4.w); iv[5] = bcast2(vr);
                #pragma unroll
                for (int c = 0; c < 3; c++) {
                    ulonglong2 wA = wt[(rr*3 + c)*2 + 0];
                    ulonglong2 wB = wt[(rr*3 + c)*2 + 1];
                    #pragma unroll
                    for (int px = 0; px < 4; px++) {
                        ull v = iv[px + c];
                        acc[px*4+0] = fma2(wA.x, v, acc[px*4+0]);
                        acc[px*4+1] = fma2(wA.y, v, acc[px*4+1]);
                        acc[px*4+2] = fma2(wB.x, v, acc[px*4+2]);
                        acc[px*4+3] = fma2(wB.y, v, acc[px*4+3]);
                    }
                }
            }
        }
    }

    bool pv[4];
    #pragma unroll
    for (int px = 0; px < 4; px++) pv[px] = jv && (k4 + px) < HY;
    const bool full4 = jv && (k4 + 3) < HY;

    #pragma unroll
    for (int cop = 0; cop < 4; cop++) {
        int coA = co0 + 2*cop, coB = coA + 1;
        float av[4], bv_[4];
        #pragma unroll
        for (int px = 0; px < 4; px++) unpack2(acc[px*4 + cop], av[px], bv_[px]);

        if (DO_STATS) {
            float sA = 0.f, qA = 0.f, sB = 0.f, qB = 0.f;
            #pragma unroll
            for (int px = 0; px < 4; px++) {
                if (pv[px]) {
                    sA += av[px]; qA += av[px]*av[px];
                    sB += bv_[px]; qB += bv_[px]*bv_[px];
                }
            }
            #pragma unroll
            for (int o = 16; o > 0; o >>= 1) {
                sA += __shfl_down_sync(0xffffffffu, sA, o);
                qA += __shfl_down_sync(0xffffffffu, qA, o);
                sB += __shfl_down_sync(0xffffffffu, sB, o);
                qB += __shfl_down_sync(0xffffffffu, qB, o);
            }
            if ((tid & 31) == 0) {
                atomicAdd(&stats[2*coA],     sA);
                atomicAdd(&stats[2*coA + 1], qA);
                atomicAdd(&stats[2*coB],     sB);
                atomicAdd(&stats[2*coB + 1], qB);
            }
        }

        float bA = HAS_BIAS ? __ldg(bias + coA) : 0.f;
        float bB = HAS_BIAS ? __ldg(bias + coB) : 0.f;
        float oA[4], oB[4];
        #pragma unroll
        for (int px = 0; px < 4; px++) {
            oA[px] = av[px] + bA; oB[px] = bv_[px] + bB;
            if (DO_RELU) { oA[px] = fmaxf(oA[px], 0.f); oB[px] = fmaxf(oB[px], 0.f); }
        }
        size_t pA = HDR + ((size_t)b*Cout + coA)*PSTR + row*PP + k4;
        size_t pB = pA + PSTR;
        if (full4) {
            *(float4*)(out + pA) = make_float4(oA[0], oA[1], oA[2], oA[3]);
            *(float4*)(out + pB) = make_float4(oB[0], oB[1], oB[2], oB[3]);
        } else {
            #pragma unroll
            for (int px = 0; px < 4; px++) {
                if (pv[px]) { out[pA + px] = oA[px]; out[pB + px] = oB[px]; }
            }
        }
    }
}

// =====================================================================
// conv3x3 v5s: SPLIT-K(2) for conv1 (CINH = 128).
// =====================================================================
template<int CINH>
__global__ void __launch_bounds__(128, 5) conv3x3_v5s(
    const float* __restrict__ in, const float* __restrict__ W,
    float* __restrict__ out0, float* __restrict__ out1, int Cout)
{
    const int b    = blockIdx.z >> 1;
    const int half = blockIdx.z & 1;
    const int co0  = blockIdx.y * 8;
    const int tid  = threadIdx.x;
    float* out = half ? out1 : out0;

    int j = blockIdx.x * 128 + tid;
    const bool jv = j < JOBS5;
    if (!jv) j = 0;
    const int row = j / NGRP;
    const int k4  = (j % NGRP) * 4;

    __shared__ __align__(16) ull sw[32*9*4];

    ull acc[16];
    #pragma unroll
    for (int i = 0; i < 16; i++) acc[i] = 0ull;

    const float* inb = in + HDR
        + ((size_t)b*(2*CINH) + (size_t)half*CINH)*PSTR + row*PP + k4;

    for (int cc = 0; cc < CINH; cc += 32) {
        __syncthreads();
        for (int i = tid; i < 8*32*9; i += 128) {
            int t  = i % 9;
            int ci = (i / 9) & 31;
            int co = i / 288;
            ((float*)sw)[(((ci*9 + t)*4 + (co >> 1)) << 1) + (co & 1)] =
                W[((size_t)(co0 + co)*(2*CINH) + half*CINH + cc + ci)*9 + t];
        }
        __syncthreads();

        #pragma unroll 1
        for (int ci = 0; ci < 32; ci++) {
            const float* pl = inb + (size_t)(cc + ci) * PSTR;
            const ulonglong2* wt = (const ulonglong2*)(sw + ci*36);
            #pragma unroll
            for (int rr = 0; rr < 3; rr++) {
                const float* pr = pl + (rr - 1) * PP;
                float4 v4 = *(const float4*)pr;
                float vl = pr[-1], vr = pr[4];
                ull iv[6];
                iv[0] = bcast2(vl);  iv[1] = bcast2(v4.x);
                iv[2] = bcast2(v4.y); iv[3] = bcast2(v4.z);
                iv[4] = bcast2(v4.w); iv[5] = bcast2(vr);
                #pragma unroll
                for (int c = 0; c < 3; c++) {
                    ulonglong2 wA = wt[(rr*3 + c)*2 + 0];
                    ulonglong2 wB = wt[(rr*3 + c)*2 + 1];
                    #pragma unroll
                    for (int px = 0; px < 4; px++) {
                        ull v = iv[px + c];
                        acc[px*4+0] = fma2(wA.x, v, acc[px*4+0]);
                        acc[px*4+1] = fma2(wA.y, v, acc[px*4+1]);
                        acc[px*4+2] = fma2(wB.x, v, acc[px*4+2]);
                        acc[px*4+3] = fma2(wB.y, v, acc[px*4+3]);
                    }
                }
            }
        }
    }

    bool pv[4];
    #pragma unroll
    for (int px = 0; px < 4; px++) pv[px] = jv && (k4 + px) < HY;
    const bool full4 = jv && (k4 + 3) < HY;

    #pragma unroll
    for (int cop = 0; cop < 4; cop++) {
        int coA = co0 + 2*cop, coB = coA + 1;
        float av[4], bv_[4];
        #pragma unroll
        for (int px = 0; px < 4; px++) unpack2(acc[px*4 + cop], av[px], bv_[px]);
        size_t pA = HDR + ((size_t)b*Cout + coA)*PSTR + row*PP + k4;
        size_t pB = pA + PSTR;
        if (full4) {
            *(float4*)(out + pA) = make_float4(av[0], av[1], av[2], av[3]);
            *(float4*)(out + pB) = make_float4(bv_[0], bv_[1], bv_[2], bv_[3]);
        } else {
            #pragma unroll
            for (int px = 0; px < 4; px++) {
                if (pv[px]) { out[pA + px] = av[px]; out[pB + px] = bv_[px]; }
            }
        }
    }
}

// =====================================================================
// conv3x3 v5q: SPLIT-K(4) for the K conv (CIN=128, quarters of 32).
// blockIdx.z = b*4 + q. Writes partials (no bias/relu) to base + q*KSTRIDE.
// =====================================================================
__global__ void __launch_bounds__(128, 5) conv3x3_v5q(
    const float* __restrict__ in, const float* __restrict__ W,
    float* __restrict__ outbase)
{
    const int b   = blockIdx.z >> 2;
    const int q   = blockIdx.z & 3;
    const int co0 = blockIdx.y * 8;
    const int tid = threadIdx.x;
    float* out = outbase + q * KSTRIDE;

    int j = blockIdx.x * 128 + tid;
    const bool jv = j < JOBS5;
    if (!jv) j = 0;
    const int row = j / NGRP;
    const int k4  = (j % NGRP) * 4;

    __shared__ __align__(16) ull sw[32*9*4];

    ull acc[16];
    #pragma unroll
    for (int i = 0; i < 16; i++) acc[i] = 0ull;

    const float* inb = in + HDR + ((size_t)b*CG + q*32)*PSTR + row*PP + k4;

    // single 32-channel chunk
    for (int i = tid; i < 8*32*9; i += 128) {
        int t  = i % 9;
        int ci = (i / 9) & 31;
        int co = i / 288;
        ((float*)sw)[(((ci*9 + t)*4 + (co >> 1)) << 1) + (co & 1)] =
            W[((size_t)(co0 + co)*CG + q*32 + ci)*9 + t];
    }
    __syncthreads();

    #pragma unroll 1
    for (int ci = 0; ci < 32; ci++) {
        const float* pl = inb + (size_t)ci * PSTR;
        const ulonglong2* wt = (const ulonglong2*)(sw + ci*36);
        #pragma unroll
        for (int rr = 0; rr < 3; rr++) {
            const float* pr = pl + (rr - 1) * PP;
            float4 v4 = *(const float4*)pr;
            float vl = pr[-1], vr = pr[4];
            ull iv[6];
            iv[0] = bcast2(vl);  iv[1] = bcast2(v4.x);
            iv[2] = bcast2(v4.y); iv[3] = bcast2(v4.z);
            iv[4] = bcast2(v4.w); iv[5] = bcast2(vr);
            #pragma unroll
            for (int c = 0; c < 3; c++) {
                ulonglong2 wA = wt[(rr*3 + c)*2 + 0];
                ulonglong2 wB = wt[(rr*3 + c)*2 + 1];
                #pragma unroll
                for (int px = 0; px < 4; px++) {
                    ull v = iv[px + c];
                    acc[px*4+0] = fma2(wA.x, v, acc[px*4+0]);
                    acc[px*4+1] = fma2(wA.y, v, acc[px*4+1]);
                    acc[px*4+2] = fma2(wB.x, v, acc[px*4+2]);
                    acc[px*4+3] = fma2(wB.y, v, acc[px*4+3]);
                }
            }
        }
    }

    bool pv[4];
    #pragma unroll
    for (int px = 0; px < 4; px++) pv[px] = jv && (k4 + px) < HY;
    const bool full4 = jv && (k4 + 3) < HY;

    #pragma unroll
    for (int cop = 0; cop < 4; cop++) {
        int coA = co0 + 2*cop, coB = coA + 1;
        float av[4], bv_[4];
        #pragma unroll
        for (int px = 0; px < 4; px++) unpack2(acc[px*4 + cop], av[px], bv_[px]);
        size_t pA = HDR + ((size_t)b*KD + coA)*PSTR + row*PP + k4;
        size_t pB = pA + PSTR;
        if (full4) {
            *(float4*)(out + pA) = make_float4(av[0], av[1], av[2], av[3]);
            *(float4*)(out + pB) = make_float4(bv_[0], bv_[1], bv_[2], bv_[3]);
        } else {
            #pragma unroll
            for (int px = 0; px < 4; px++) {
                if (pv[px]) { out[pA + px] = av[px]; out[pB + px] = bv_[px]; }
            }
        }
    }
}

// ---------------- combine K partials: g_k = relu(sum_q partial_q + bk) ------
__global__ void combine_k(const float* __restrict__ parts,
                          const float* __restrict__ bk,
                          float* __restrict__ outk) {
    int idx = blockIdx.x * 256 + threadIdx.x;
    if (idx >= BB*KD*CHUNKS) return;
    int plane = idx / CHUNKS;
    int ch    = idx % CHUNKS;
    int d = plane % KD;
    float bias = __ldg(bk + d);
    size_t a = HDR + (size_t)plane*PSTR + (size_t)ch*4;
    float4 s = *(const float4*)(parts + a);
    #pragma unroll
    for (int q = 1; q < 4; q++) {
        float4 v = *(const float4*)(parts + q*KSTRIDE + a);
        s.x += v.x; s.y += v.y; s.z += v.z; s.w += v.w;
    }
    float4 o;
    o.x = fmaxf(s.x + bias, 0.f);
    o.y = fmaxf(s.y + bias, 0.f);
    o.z = fmaxf(s.z + bias, 0.f);
    o.w = fmaxf(s.w + bias, 0.f);
    *(float4*)(outk + a) = o;
}

// ---------------- sum partials in place + per-channel stats (float4) --------
__global__ void sum_stats_v2(float* __restrict__ t0,
                             const float* __restrict__ t1,
                             float* __restrict__ stats) {
    int plane = blockIdx.x;
    int c = plane % CG;
    int tid = threadIdx.x;
    size_t base = HDR + (size_t)plane * PSTR;
    float s = 0.f, q = 0.f;
    for (int ch = tid; ch < CHUNKS; ch += 256) {
        size_t a = base + ch * 4;
        float4 v0 = *(const float4*)(t0 + a);
        float4 v1 = *(const float4*)(t1 + a);
        float4 v = make_float4(v0.x+v1.x, v0.y+v1.y, v0.z+v1.z, v0.w+v1.w);
        *(float4*)(t0 + a) = v;
        s += v.x + v.y + v.z + v.w;
        q += v.x*v.x + v.y*v.y + v.z*v.z + v.w*v.w;
    }
    #pragma unroll
    for (int o = 16; o > 0; o >>= 1) {
        s += __shfl_down_sync(0xffffffffu, s, o);
        q += __shfl_down_sync(0xffffffffu, q, o);
    }
    __shared__ float rs[8], rq[8];
    int w = tid >> 5;
    if ((tid & 31) == 0) { rs[w] = s; rq[w] = q; }
    __syncthreads();
    if (tid == 0) {
        float S = 0.f, Q = 0.f;
        #pragma unroll
        for (int i = 0; i < 8; i++) { S += rs[i]; Q += rq[i]; }
        atomicAdd(&stats[2*c],     S);
        atomicAdd(&stats[2*c + 1], Q);
    }
}

// ---------------- BN+ReLU padded->padded, float4, pads forced to 0 ----------
__global__ void bn_relu_pad(const float* __restrict__ t,
                            const float* __restrict__ stats,
                            const float* __restrict__ gamma,
                            const float* __restrict__ beta,
                            float* __restrict__ out) {
    int idx = blockIdx.x * 256 + threadIdx.x;
    if (idx >= BB*CG*CHUNKS) return;
    int plane = idx / CHUNKS;
    int ch    = idx % CHUNKS;
    int row   = ch / NGRP;
    int c4    = (ch % NGRP) * 4;
    int c = plane % CG;
    float m   = stats[2*c]   * (1.f/NBHW);
    float var = stats[2*c+1] * (1.f/NBHW) - m*m;
    float sc  = gamma[c] * rsqrtf(fmaxf(var, 0.f) + EPSB);
    float sh  = beta[c] - sc * m;
    size_t a = HDR + (size_t)plane*PSTR + (size_t)ch*4;
    float4 v = *(const float4*)(t + a);
    float4 o;
    o.x = fmaxf(sc*v.x + sh, 0.f);
    o.y = fmaxf(sc*v.y + sh, 0.f);
    o.z = fmaxf(sc*v.z + sh, 0.f);
    o.w = fmaxf(sc*v.w + sh, 0.f);
    if (row >= HY) { o.x = o.y = o.z = o.w = 0.f; }
    else {
        if (c4 + 0 >= HY) o.x = 0.f;
        if (c4 + 1 >= HY) o.y = 0.f;
        if (c4 + 2 >= HY) o.z = 0.f;
        if (c4 + 3 >= HY) o.w = 0.f;
    }
    *(float4*)(out + a) = o;
}

// ---------------- BN+ReLU padded -> flat output ------------------------------
__global__ void bn_relu_out(const float* __restrict__ t,
                            const float* __restrict__ stats,
                            const float* __restrict__ gamma,
                            const float* __restrict__ beta,
                            float* __restrict__ out) {
    int i = blockIdx.x * blockDim.x + threadIdx.x;
    if (i >= BB*CG*NPIX) return;
    int plane = i / NPIX;
    int pix   = i % NPIX;
    int row = pix / HY, col = pix % HY;
    int c = plane % CG;
    size_t ain = HDR + (size_t)plane*PSTR + row*PP + col;
    float v = t[ain];
    float m   = stats[2*c]   * (1.f/NBHW);
    float var = stats[2*c+1] * (1.f/NBHW) - m*m;
    float sc  = gamma[c] * rsqrtf(fmaxf(var, 0.f) + EPSB);
    out[i] = fmaxf(sc * (v - m) + beta[c], 0.f);
}

// =====================================================================
// ConvTranspose: all 4 parity classes in ONE kernel.
// =====================================================================
template<int NTH, int NTW>
__device__ __forceinline__ void convt_body(
    const float* __restrict__ x, const float* __restrict__ Wt,
    const float* __restrict__ bt, ull* swt, int b, int co0, int bx, int tid)
{
    constexpr int NT  = NTH * NTW;
    constexpr int PY  = (NTH == 2) ? 0 : 1;
    constexpr int PXP = (NTW == 2) ? 0 : 1;
    constexpr int CXN = (PXP == 0) ? 33 : 32;
    constexpr int RY  = (PY  == 0) ? 33 : 32;
    constexpr int NPC = RY * CXN;

    if (bx * 128 >= (NPC + 1) / 2) return;

    const int pair = bx * 128 + tid;
    const int p0 = pair*2, p1 = p0 + 1;
    const bool v0 = p0 < NPC, v1 = p1 < NPC;
    const int cr0 = v0 ? p0 / CXN : 0, cc0_ = v0 ? p0 % CXN : 0;
    const int cr1 = v1 ? p1 / CXN : 0, cc1_ = v1 ? p1 % CXN : 0;

    bool ok0[NT], ok1[NT];
    int  io0[NT], io1[NT];
    #pragma unroll
    for (int tt = 0; tt < NT; tt++) {
        int th = tt / NTW, tw = tt % NTW;
        int iy0 = cr0 - th, ix0 = cc0_ - tw;
        ok0[tt] = v0 && iy0 >= 0 && iy0 < HX && ix0 >= 0 && ix0 < HX;
        io0[tt] = iy0 * HX + ix0;
        int iy1 = cr1 - th, ix1 = cc1_ - tw;
        ok1[tt] = v1 && iy1 >= 0 && iy1 < HX && ix1 >= 0 && ix1 < HX;
        io1[tt] = iy1 * HX + ix1;
    }

    ull accA[8], accB[8];
    #pragma unroll
    for (int i = 0; i < 8; i++) { accA[i] = 0ull; accB[i] = 0ull; }

    const float* xb = x + (size_t)b * CX * HX * HX;

    for (int cc = 0; cc < CX; cc += 32) {
        __syncthreads();
        for (int i = tid; i < 16*32*NT; i += 128) {
            int tt = i % NT;
            int ci = (i / NT) & 31;
            int co = i / (NT * 32);
            int th = tt / NTW, tw = tt % NTW;
            int kh = (NTH == 2) ? 2*th : 1;
            int kw = (NTW == 2) ? 2*tw : 1;
            ((float*)swt)[((ci*8 + (co>>1))*NT + tt)*2 + (co&1)] =
                Wt[((size_t)(co0 + co)*CX + cc + ci)*9 + kh*3 + kw];
        }
        __syncthreads();

        #pragma unroll 1
        for (int ci = 0; ci < 32; ci++) {
            const float* pl = xb + (size_t)(cc + ci) * (HX * HX);
            ull in0[NT], in1[NT];
            #pragma unroll
            for (int tt = 0; tt < NT; tt++) {
                float a  = ok0[tt] ? __ldg(pl + io0[tt]) : 0.f;
                float bb = ok1[tt] ? __ldg(pl + io1[tt]) : 0.f;
                in0[tt] = bcast2(a);
                in1[tt] = bcast2(bb);
            }
            const ull* wbase = swt + ci * 8 * NT;
            #pragma unroll
            for (int cop = 0; cop < 8; cop++) {
                ull w[NT];
                if constexpr (NT == 4) {
                    const ulonglong2* qq = (const ulonglong2*)(wbase + cop*4);
                    ulonglong2 q0 = qq[0], q1 = qq[1];
                    w[0] = q0.x; w[1] = q0.y; w[2] = q1.x; w[3] = q1.y;
                } else if constexpr (NT == 2) {
                    ulonglong2 q0 = ((const ulonglong2*)(wbase + cop*2))[0];
                    w[0] = q0.x; w[1] = q0.y;
                } else {
                    w[0] = wbase[cop];
                }
                ull a = accA[cop], bb2 = accB[cop];
                #pragma unroll
                for (int tt = 0; tt < NT; tt++) {
                    a   = fma2(w[tt], in0[tt], a);
                    bb2 = fma2(w[tt], in1[tt], bb2);
                }
                accA[cop] = a; accB[cop] = bb2;
            }
        }
    }

    const int oy0 = 2*cr0 + PY, ox0 = 2*cc0_ + PXP;
    const int oy1 = 2*cr1 + PY, ox1 = 2*cc1_ + PXP;
    #pragma unroll
    for (int cop = 0; cop < 8; cop++) {
        float a0, a1, b0, b1;
        unpack2(accA[cop], a0, a1);
        unpack2(accB[cop], b0, b1);
        int coA = co0 + 2*cop, coB = coA + 1;
        float bA = __ldg(bt + coA), bB = __ldg(bt + coB);
        if (v0) {
            size_t qq = HDR + ((size_t)b*CX + coA)*PSTR + oy0*PP + ox0;
            g_h[qq]        = fmaxf(a0 + bA, 0.f);
            g_h[qq + PSTR] = fmaxf(a1 + bB, 0.f);
        }
        if (v1) {
            size_t qq = HDR + ((size_t)b*CX + coA)*PSTR + oy1*PP + ox1;
            g_h[qq]        = fmaxf(b0 + bA, 0.f);
            g_h[qq + PSTR] = fmaxf(b1 + bB, 0.f);
        }
    }
}

__global__ void __launch_bounds__(128, 5) convt_all(
    const float* __restrict__ x, const float* __restrict__ Wt,
    const float* __restrict__ bt)
{
    __shared__ __align__(16) ull swt[32 * 8 * 4];
    const int b   = blockIdx.z >> 2;
    const int cls = blockIdx.z & 3;
    const int co0 = blockIdx.y * 16;
    const int tid = threadIdx.x;
    const int bx  = blockIdx.x;
    switch (cls) {
        case 0: convt_body<2,2>(x, Wt, bt, swt, b, co0, bx, tid); break;
        case 1: convt_body<2,1>(x, Wt, bt, swt, b, co0, bx, tid); break;
        case 2: convt_body<1,2>(x, Wt, bt, swt, b, co0, bx, tid); break;
        default: convt_body<1,1>(x, Wt, bt, swt, b, co0, bx, tid); break;
    }
}

// ---------------- fused gate: depthwise Q + softmax over KD keys ------------
__global__ void gate_kernel(const float* __restrict__ y,
                            const float* __restrict__ Wq,
                            const float* __restrict__ bq,
                            const float* __restrict__ Wv,
                            const float* __restrict__ bv) {
    __shared__ float swv[KD], sbv[KD], swq[9];
    __shared__ float sbq;
    int tid = threadIdx.x;
    int zc = blockIdx.y;
    int c  = zc % CG;
    int b  = zc / CG;
    if (tid < KD) { swv[tid] = Wv[tid]; sbv[tid] = bv[tid]; }
    if (tid < 9)  swq[tid] = Wq[c * 9 + tid];
    if (tid == 9) sbq = bq[c];
    __syncthreads();

    int pix = blockIdx.x * 256 + tid;
    if (pix >= NPIX) return;
    int oy = pix / HY, ox = pix % HY;

    const float* p = y + ((size_t)b * CG + c) * NPIX;
    float qv = sbq;
    #pragma unroll
    for (int ky = 0; ky < 3; ky++) {
        int iy = oy + ky - 1;
        if (iy < 0 || iy >= HY) continue;
        #pragma unroll
        for (int kx = 0; kx < 3; kx++) {
            int ix = ox + kx - 1;
            if (ix < 0 || ix >= HY) continue;
            qv += __ldg(p + iy * HY + ix) * swq[ky * 3 + kx];
        }
    }
    qv = fmaxf(qv, 0.f);

    float yv = __ldg(p + pix);
    const float* kp = g_k + HDR + (size_t)b * KD * PSTR + oy*PP + ox;

    float s[KD];
    float mx = -1e30f;
    #pragma unroll
    for (int d = 0; d < KD; d++) {
        s[d] = qv * __ldg(kp + (size_t)d * PSTR);
        mx = fmaxf(mx, s[d]);
    }
    float se = 0.f, num = 0.f;
    #pragma unroll
    for (int d = 0; d < KD; d++) {
        float e = __expf(s[d] - mx);
        se  += e;
        num += e * fmaxf(yv * swv[d] + sbv[d], 0.f);
    }
    g_g[HDR + ((size_t)b * CG + c) * PSTR + oy*PP + ox] = num / se;
}

// ---------------- host launch -----------------------------------------------
extern "C" void kernel_launch(void* const* d_in, const int* in_sizes, int n_in,
                              void* d_out, int out_size) {
    const float* x  = (const float*)d_in[0];
    const float* y  = (const float*)d_in[1];
    const float* Wt = (const float*)d_in[2];
    const float* bt = (const float*)d_in[3];
    const float* W1 = (const float*)d_in[4];
    const float* g1 = (const float*)d_in[5];
    const float* b1 = (const float*)d_in[6];
    const float* W2 = (const float*)d_in[7];
    const float* g2 = (const float*)d_in[8];
    const float* b2 = (const float*)d_in[9];
    const float* Wq = (const float*)d_in[10];
    const float* bq = (const float*)d_in[11];
    const float* Wk = (const float*)d_in[12];
    const float* bk = (const float*)d_in[13];
    const float* Wv = (const float*)d_in[14];
    const float* bv = (const float*)d_in[15];
    const float* W3 = (const float*)d_in[16];
    const float* g3 = (const float*)d_in[17];
    const float* b3 = (const float*)d_in[18];
    const float* W4 = (const float*)d_in[19];
    const float* g4 = (const float*)d_in[20];
    const float* b4 = (const float*)d_in[21];
    float* out = (float*)d_out;

    float *p_h, *p_tmp, *p_a, *p_xu, *p_k, *p_g, *p_o1, *p_stats;
    cudaGetSymbolAddress((void**)&p_h,     g_h);
    cudaGetSymbolAddress((void**)&p_tmp,   g_tmp);
    cudaGetSymbolAddress((void**)&p_a,     g_a);
    cudaGetSymbolAddress((void**)&p_xu,    g_xu);
    cudaGetSymbolAddress((void**)&p_k,     g_k);
    cudaGetSymbolAddress((void**)&p_g,     g_g);
    cudaGetSymbolAddress((void**)&p_o1,    g_o1);
    cudaGetSymbolAddress((void**)&p_stats, g_stats);

    const int BJ = (JOBS5 + 127) / 128;     // 9
    dim3 grdS (BJ, CG/8, BB*2);             // split conv1: 1152 blocks
    dim3 grdCG(BJ, CG/8, BB);               // unsplit CG convs: 576 blocks
    dim3 grdKQ(BJ, KD/8, BB*4);             // split-4 K conv: 576 blocks
    int  elems  = BB * CG * NPIX;
    int  eb     = (elems + 255) / 256;
    int  planes = BB * CG;                  // 512
    int  padBlocks = (planes * CHUNKS + 255) / 256;
    int  kBlocks   = (BB * KD * CHUNKS + 255) / 256;

    zero_stats_kernel<<<1, 1024>>>();
    convt_all<<<dim3(5, CX/16, BB*4), 128>>>(x, Wt, bt);

    // conv1 (256 -> 128): split-K(2)
    conv3x3_v5s<128><<<grdS, 128>>>(p_h, W1, p_tmp, p_o1, CG);
    sum_stats_v2<<<planes, 256>>>(p_tmp, p_o1, p_stats + 0);
    bn_relu_pad<<<padBlocks, 256>>>(p_tmp, p_stats + 0, g1, b1, p_a);

    // conv2 (128 -> 128): unsplit, fused stats
    conv3x3_v5<CG, false, true, false><<<grdCG, 128>>>(p_a, W2, nullptr, p_tmp, p_stats + 2*CG, CG);
    bn_relu_pad<<<padBlocks, 256>>>(p_tmp, p_stats + 2*CG, g2, b2, p_xu);

    // K conv (128 -> 32): split-K(4) into g_tmp quarters, then combine
    conv3x3_v5q<<<grdKQ, 128>>>(p_xu, Wk, p_tmp);
    combine_k<<<kBlocks, 256>>>(p_tmp, bk, p_k);
    gate_kernel<<<dim3((NPIX + 255)/256, BB*CG), 256>>>(y, Wq, bq, Wv, bv);

    // final DoubleConv (128 -> 128): unsplit, fused stats
    conv3x3_v5<CG, false, true, false><<<grdCG, 128>>>(p_g, W3, nullptr, p_tmp, p_stats + 4*CG, CG);
    bn_relu_pad<<<padBlocks, 256>>>(p_tmp, p_stats + 4*CG, g3, b3, p_o1);
    conv3x3_v5<CG, false, true, false><<<grdCG, 128>>>(p_o1, W4, nullptr, p_tmp, p_stats + 6*CG, CG);
    bn_relu_out<<<eb, 256>>>(p_tmp, p_stats + 6*CG, g4, b4, out);
}

// round 16
// speedup vs baseline: 1.3219x; 1.0120x over previous
#include <cuda_runtime.h>
#include <math.h>

// ---------------- problem constants ----------------
#define BB   4
#define CX   256
#define HX   32
#define HY   65
#define NPIX (HY*HY)   // 4225
#define CG   128
#define KD   32
#define NBHW 16900.0f
#define EPSB 1e-5f

#define PP    68
#define PROWS 66
#define PSTR  (PROWS*PP)  // 4488 floats per plane
#define HDR   (PP + 4)
#define NGRP  17
#define JOBS5 (HY*NGRP)   // 1105
#define CHUNKS (PROWS*NGRP) // 1122
#define KSTRIDE ((size_t)BB*KD*PSTR)

typedef unsigned long long ull;

__device__ __forceinline__ ull pack2(float a, float b) {
    ull r; asm("mov.b64 %0, {%1,%2};" : "=l"(r) : "f"(a), "f"(b)); return r;
}
__device__ __forceinline__ ull bcast2(float a) { return pack2(a, a); }
__device__ __forceinline__ void unpack2(ull v, float& a, float& b) {
    asm("mov.b64 {%0,%1}, %2;" : "=f"(a), "=f"(b) : "l"(v));
}
__device__ __forceinline__ ull fma2(ull a, ull b, ull c) {
    ull d; asm("fma.rn.f32x2 %0, %1, %2, %3;" : "=l"(d) : "l"(a), "l"(b), "l"(c)); return d;
}

// ---------------- scratch ----------
__device__ __align__(16) float g_h  [HDR + BB*CX*PSTR + 256];
__device__ __align__(16) float g_tmp[HDR + BB*CG*PSTR + 256];
__device__ __align__(16) float g_a  [HDR + BB*CG*PSTR + 256];
__device__ __align__(16) float g_xu [HDR + BB*CG*PSTR + 256];
__device__ __align__(16) float g_k  [HDR + BB*KD*PSTR + 256];
__device__ __align__(16) float g_g  [HDR + BB*CG*PSTR + 256];
__device__ __align__(16) float g_o1 [HDR + BB*CG*PSTR + 256];
__device__ float g_stats[4*2*CG];

// ---------------- prefetch helpers ----------------
struct InRegs { float4 v4[3]; float vl[3], vr[3]; };

__device__ __forceinline__ void load_in(const float* pl, InRegs& r) {
    #pragma unroll
    for (int rr = 0; rr < 3; rr++) {
        const float* pr = pl + (rr - 1) * PP;
        r.v4[rr] = *(const float4*)pr;
        r.vl[rr] = pr[-1];
        r.vr[rr] = pr[4];
    }
}

// fma block: 144 fma2 over acc[16] given InRegs + weight base (ci*36 floats)
__device__ __forceinline__ void fma_block(const InRegs& r, const ulonglong2* wt, ull* acc) {
    #pragma unroll
    for (int rr = 0; rr < 3; rr++) {
        ull iv[6];
        iv[0] = bcast2(r.vl[rr]);  iv[1] = bcast2(r.v4[rr].x);
        iv[2] = bcast2(r.v4[rr].y); iv[3] = bcast2(r.v4[rr].z);
        iv[4] = bcast2(r.v4[rr].w); iv[5] = bcast2(r.vr[rr]);
        #pragma unroll
        for (int c = 0; c < 3; c++) {
            ulonglong2 wA = wt[(rr*3 + c)*2 + 0];
            ulonglong2 wB = wt[(rr*3 + c)*2 + 1];
            #pragma unroll
            for (int px = 0; px < 4; px++) {
                ull v = iv[px + c];
                acc[px*4+0] = fma2(wA.x, v, acc[px*4+0]);
                acc[px*4+1] = fma2(wA.y, v, acc[px*4+1]);
                acc[px*4+2] = fma2(wB.x, v, acc[px*4+2]);
                acc[px*4+3] = fma2(wB.y, v, acc[px*4+3]);
            }
        }
    }
}

// =====================================================================
// conv3x3 v5p: proven v5 tiling + double-buffered input prefetch.
// =====================================================================
template<int CIN, bool HAS_BIAS, bool DO_STATS, bool DO_RELU>
__global__ void __launch_bounds__(128, 4) conv3x3_v5p(
    const float* __restrict__ in, const float* __restrict__ W,
    const float* __restrict__ bias, float* __restrict__ out,
    float* __restrict__ stats, int Cout)
{
    const int b   = blockIdx.z;
    const int co0 = blockIdx.y * 8;
    const int tid = threadIdx.x;
    int j = blockIdx.x * 128 + tid;
    const bool jv = j < JOBS5;
    if (!jv) j = 0;
    const int row = j / NGRP;
    const int k4  = (j % NGRP) * 4;

    __shared__ __align__(16) ull sw[32*9*4];

    ull acc[16];
    #pragma unroll
    for (int i = 0; i < 16; i++) acc[i] = 0ull;

    const float* inb = in + HDR + (size_t)b*CIN*PSTR + row*PP + k4;

    for (int cc = 0; cc < CIN; cc += 32) {
        __syncthreads();
        for (int i = tid; i < 8*32*9; i += 128) {
            int t  = i % 9;
            int ci = (i / 9) & 31;
            int co = i / 288;
            ((float*)sw)[(((ci*9 + t)*4 + (co >> 1)) << 1) + (co & 1)] =
                W[((size_t)(co0 + co)*CIN + cc + ci)*9 + t];
        }
        __syncthreads();

        const float* base = inb + (size_t)cc * PSTR;
        InRegs cur, nxt;
        load_in(base, cur);
        #pragma unroll 1
        for (int ci = 0; ci < 32; ci++) {
            if (ci < 31) load_in(base + (size_t)(ci + 1) * PSTR, nxt);
            fma_block(cur, (const ulonglong2*)(sw + ci*36), acc);
            cur = nxt;
        }
    }

    bool pv[4];
    #pragma unroll
    for (int px = 0; px < 4; px++) pv[px] = jv && (k4 + px) < HY;
    const bool full4 = jv && (k4 + 3) < HY;

    #pragma unroll
    for (int cop = 0; cop < 4; cop++) {
        int coA = co0 + 2*cop, coB = coA + 1;
        float av[4], bv_[4];
        #pragma unroll
        for (int px = 0; px < 4; px++) unpack2(acc[px*4 + cop], av[px], bv_[px]);

        if (DO_STATS) {
            float sA = 0.f, qA = 0.f, sB = 0.f, qB = 0.f;
            #pragma unroll
            for (int px = 0; px < 4; px++) {
                if (pv[px]) {
                    sA += av[px]; qA += av[px]*av[px];
                    sB += bv_[px]; qB += bv_[px]*bv_[px];
                }
            }
            #pragma unroll
            for (int o = 16; o > 0; o >>= 1) {
                sA += __shfl_down_sync(0xffffffffu, sA, o);
                qA += __shfl_down_sync(0xffffffffu, qA, o);
                sB += __shfl_down_sync(0xffffffffu, sB, o);
                qB += __shfl_down_sync(0xffffffffu, qB, o);
            }
            if ((tid & 31) == 0) {
                atomicAdd(&stats[2*coA],     sA);
                atomicAdd(&stats[2*coA + 1], qA);
                atomicAdd(&stats[2*coB],     sB);
                atomicAdd(&stats[2*coB + 1], qB);
            }
        }

        float bA = HAS_BIAS ? __ldg(bias + coA) : 0.f;
        float bB = HAS_BIAS ? __ldg(bias + coB) : 0.f;
        float oA[4], oB[4];
        #pragma unroll
        for (int px = 0; px < 4; px++) {
            oA[px] = av[px] + bA; oB[px] = bv_[px] + bB;
            if (DO_RELU) { oA[px] = fmaxf(oA[px], 0.f); oB[px] = fmaxf(oB[px], 0.f); }
        }
        size_t pA = HDR + ((size_t)b*Cout + coA)*PSTR + row*PP + k4;
        size_t pB = pA + PSTR;
        if (full4) {
            *(float4*)(out + pA) = make_float4(oA[0], oA[1], oA[2], oA[3]);
            *(float4*)(out + pB) = make_float4(oB[0], oB[1], oB[2], oB[3]);
        } else {
            #pragma unroll
            for (int px = 0; px < 4; px++) {
                if (pv[px]) { out[pA + px] = oA[px]; out[pB + px] = oB[px]; }
            }
        }
    }
}

// =====================================================================
// conv3x3 v5sp: SPLIT-K(2) for conv1 + prefetch.
// =====================================================================
template<int CINH>
__global__ void __launch_bounds__(128, 4) conv3x3_v5sp(
    const float* __restrict__ in, const float* __restrict__ W,
    float* __restrict__ out0, float* __restrict__ out1, int Cout)
{
    const int b    = blockIdx.z >> 1;
    const int half = blockIdx.z & 1;
    const int co0  = blockIdx.y * 8;
    const int tid  = threadIdx.x;
    float* out = half ? out1 : out0;

    int j = blockIdx.x * 128 + tid;
    const bool jv = j < JOBS5;
    if (!jv) j = 0;
    const int row = j / NGRP;
    const int k4  = (j % NGRP) * 4;

    __shared__ __align__(16) ull sw[32*9*4];

    ull acc[16];
    #pragma unroll
    for (int i = 0; i < 16; i++) acc[i] = 0ull;

    const float* inb = in + HDR
        + ((size_t)b*(2*CINH) + (size_t)half*CINH)*PSTR + row*PP + k4;

    for (int cc = 0; cc < CINH; cc += 32) {
        __syncthreads();
        for (int i = tid; i < 8*32*9; i += 128) {
            int t  = i % 9;
            int ci = (i / 9) & 31;
            int co = i / 288;
            ((float*)sw)[(((ci*9 + t)*4 + (co >> 1)) << 1) + (co & 1)] =
                W[((size_t)(co0 + co)*(2*CINH) + half*CINH + cc + ci)*9 + t];
        }
        __syncthreads();

        const float* base = inb + (size_t)cc * PSTR;
        InRegs cur, nxt;
        load_in(base, cur);
        #pragma unroll 1
        for (int ci = 0; ci < 32; ci++) {
            if (ci < 31) load_in(base + (size_t)(ci + 1) * PSTR, nxt);
            fma_block(cur, (const ulonglong2*)(sw + ci*36), acc);
            cur = nxt;
        }
    }

    bool pv[4];
    #pragma unroll
    for (int px = 0; px < 4; px++) pv[px] = jv && (k4 + px) < HY;
    const bool full4 = jv && (k4 + 3) < HY;

    #pragma unroll
    for (int cop = 0; cop < 4; cop++) {
        int coA = co0 + 2*cop, coB = coA + 1;
        float av[4], bv_[4];
        #pragma unroll
        for (int px = 0; px < 4; px++) unpack2(acc[px*4 + cop], av[px], bv_[px]);
        size_t pA = HDR + ((size_t)b*Cout + coA)*PSTR + row*PP + k4;
        size_t pB = pA + PSTR;
        if (full4) {
            *(float4*)(out + pA) = make_float4(av[0], av[1], av[2], av[3]);
            *(float4*)(out + pB) = make_float4(bv_[0], bv_[1], bv_[2], bv_[3]);
        } else {
            #pragma unroll
            for (int px = 0; px < 4; px++) {
                if (pv[px]) { out[pA + px] = av[px]; out[pB + px] = bv_[px]; }
            }
        }
    }
}

// =====================================================================
// conv3x3 v5qp: SPLIT-K(4) for K conv + prefetch.
// =====================================================================
__global__ void __launch_bounds__(128, 4) conv3x3_v5qp(
    const float* __restrict__ in, const float* __restrict__ W,
    float* __restrict__ outbase)
{
    const int b   = blockIdx.z >> 2;
    const int q   = blockIdx.z & 3;
    const int co0 = blockIdx.y * 8;
    const int tid = threadIdx.x;
    float* out = outbase + q * KSTRIDE;

    int j = blockIdx.x * 128 + tid;
    const bool jv = j < JOBS5;
    if (!jv) j = 0;
    const int row = j / NGRP;
    const int k4  = (j % NGRP) * 4;

    __shared__ __align__(16) ull sw[32*9*4];

    ull acc[16];
    #pragma unroll
    for (int i = 0; i < 16; i++) acc[i] = 0ull;

    const float* inb = in + HDR + ((size_t)b*CG + q*32)*PSTR + row*PP + k4;

    for (int i = tid; i < 8*32*9; i += 128) {
        int t  = i % 9;
        int ci = (i / 9) & 31;
        int co = i / 288;
        ((float*)sw)[(((ci*9 + t)*4 + (co >> 1)) << 1) + (co & 1)] =
            W[((size_t)(co0 + co)*CG + q*32 + ci)*9 + t];
    }
    __syncthreads();

    InRegs cur, nxt;
    load_in(inb, cur);
    #pragma unroll 1
    for (int ci = 0; ci < 32; ci++) {
        if (ci < 31) load_in(inb + (size_t)(ci + 1) * PSTR, nxt);
        fma_block(cur, (const ulonglong2*)(sw + ci*36), acc);
        cur = nxt;
    }

    bool pv[4];
    #pragma unroll
    for (int px = 0; px < 4; px++) pv[px] = jv && (k4 + px) < HY;
    const bool full4 = jv && (k4 + 3) < HY;

    #pragma unroll
    for (int cop = 0; cop < 4; cop++) {
        int coA = co0 + 2*cop, coB = coA + 1;
        float av[4], bv_[4];
        #pragma unroll
        for (int px = 0; px < 4; px++) unpack2(acc[px*4 + cop], av[px], bv_[px]);
        size_t pA = HDR + ((size_t)b*KD + coA)*PSTR + row*PP + k4;
        size_t pB = pA + PSTR;
        if (full4) {
            *(float4*)(out + pA) = make_float4(av[0], av[1], av[2], av[3]);
            *(float4*)(out + pB) = make_float4(bv_[0], bv_[1], bv_[2], bv_[3]);
        } else {
            #pragma unroll
            for (int px = 0; px < 4; px++) {
                if (pv[px]) { out[pA + px] = av[px]; out[pB + px] = bv_[px]; }
            }
        }
    }
}

// ---------------- combine K partials ------
__global__ void combine_k(const float* __restrict__ parts,
                          const float* __restrict__ bk,
                          float* __restrict__ outk) {
    int idx = blockIdx.x * 256 + threadIdx.x;
    if (idx >= BB*KD*CHUNKS) return;
    int plane = idx / CHUNKS;
    int ch    = idx % CHUNKS;
    int d = plane % KD;
    float bias = __ldg(bk + d);
    size_t a = HDR + (size_t)plane*PSTR + (size_t)ch*4;
    float4 s = *(const float4*)(parts + a);
    #pragma unroll
    for (int q = 1; q < 4; q++) {
        float4 v = *(const float4*)(parts + q*KSTRIDE + a);
        s.x += v.x; s.y += v.y; s.z += v.z; s.w += v.w;
    }
    float4 o;
    o.x = fmaxf(s.x + bias, 0.f);
    o.y = fmaxf(s.y + bias, 0.f);
    o.z = fmaxf(s.z + bias, 0.f);
    o.w = fmaxf(s.w + bias, 0.f);
    *(float4*)(outk + a) = o;
}

// ---------------- sum partials + stats (float4) --------
__global__ void sum_stats_v2(float* __restrict__ t0,
                             const float* __restrict__ t1,
                             float* __restrict__ stats) {
    int plane = blockIdx.x;
    int c = plane % CG;
    int tid = threadIdx.x;
    size_t base = HDR + (size_t)plane * PSTR;
    float s = 0.f, q = 0.f;
    for (int ch = tid; ch < CHUNKS; ch += 256) {
        size_t a = base + ch * 4;
        float4 v0 = *(const float4*)(t0 + a);
        float4 v1 = *(const float4*)(t1 + a);
        float4 v = make_float4(v0.x+v1.x, v0.y+v1.y, v0.z+v1.z, v0.w+v1.w);
        *(float4*)(t0 + a) = v;
        s += v.x + v.y + v.z + v.w;
        q += v.x*v.x + v.y*v.y + v.z*v.z + v.w*v.w;
    }
    #pragma unroll
    for (int o = 16; o > 0; o >>= 1) {
        s += __shfl_down_sync(0xffffffffu, s, o);
        q += __shfl_down_sync(0xffffffffu, q, o);
    }
    __shared__ float rs[8], rq[8];
    int w = tid >> 5;
    if ((tid & 31) == 0) { rs[w] = s; rq[w] = q; }
    __syncthreads();
    if (tid == 0) {
        float S = 0.f, Q = 0.f;
        #pragma unroll
        for (int i = 0; i < 8; i++) { S += rs[i]; Q += rq[i]; }
        atomicAdd(&stats[2*c],     S);
        atomicAdd(&stats[2*c + 1], Q);
    }
}

// ---------------- BN+ReLU padded->padded --------
__global__ void bn_relu_pad(const float* __restrict__ t,
                            const float* __restrict__ stats,
                            const float* __restrict__ gamma,
                            const float* __restrict__ beta,
                            float* __restrict__ out) {
    int idx = blockIdx.x * 256 + threadIdx.x;
    if (idx >= BB*CG*CHUNKS) return;
    int plane = idx / CHUNKS;
    int ch    = idx % CHUNKS;
    int row   = ch / NGRP;
    int c4    = (ch % NGRP) * 4;
    int c = plane % CG;
    float m   = stats[2*c]   * (1.f/NBHW);
    float var = stats[2*c+1] * (1.f/NBHW) - m*m;
    float sc  = gamma[c] * rsqrtf(fmaxf(var, 0.f) + EPSB);
    float sh  = beta[c] - sc * m;
    size_t a = HDR + (size_t)plane*PSTR + (size_t)ch*4;
    float4 v = *(const float4*)(t + a);
    float4 o;
    o.x = fmaxf(sc*v.x + sh, 0.f);
    o.y = fmaxf(sc*v.y + sh, 0.f);
    o.z = fmaxf(sc*v.z + sh, 0.f);
    o.w = fmaxf(sc*v.w + sh, 0.f);
    if (row >= HY) { o.x = o.y = o.z = o.w = 0.f; }
    else {
        if (c4 + 0 >= HY) o.x = 0.f;
        if (c4 + 1 >= HY) o.y = 0.f;
        if (c4 + 2 >= HY) o.z = 0.f;
        if (c4 + 3 >= HY) o.w = 0.f;
    }
    *(float4*)(out + a) = o;
}

// ---------------- BN+ReLU padded -> flat output ------------------------------
__global__ void bn_relu_out(const float* __restrict__ t,
                            const float* __restrict__ stats,
                            const float* __restrict__ gamma,
                            const float* __restrict__ beta,
                            float* __restrict__ out) {
    int i = blockIdx.x * blockDim.x + threadIdx.x;
    if (i >= BB*CG*NPIX) return;
    int plane = i / NPIX;
    int pix   = i % NPIX;
    int row = pix / HY, col = pix % HY;
    int c = plane % CG;
    size_t ain = HDR + (size_t)plane*PSTR + row*PP + col;
    float v = t[ain];
    float m   = stats[2*c]   * (1.f/NBHW);
    float var = stats[2*c+1] * (1.f/NBHW) - m*m;
    float sc  = gamma[c] * rsqrtf(fmaxf(var, 0.f) + EPSB);
    out[i] = fmaxf(sc * (v - m) + beta[c], 0.f);
}

// =====================================================================
// ConvTranspose (4 classes, one kernel) + inline stats zeroing.
// =====================================================================
template<int NTH, int NTW>
__device__ __forceinline__ void convt_body(
    const float* __restrict__ x, const float* __restrict__ Wt,
    const float* __restrict__ bt, ull* swt, int b, int co0, int bx, int tid)
{
    constexpr int NT  = NTH * NTW;
    constexpr int PY  = (NTH == 2) ? 0 : 1;
    constexpr int PXP = (NTW == 2) ? 0 : 1;
    constexpr int CXN = (PXP == 0) ? 33 : 32;
    constexpr int RY  = (PY  == 0) ? 33 : 32;
    constexpr int NPC = RY * CXN;

    if (bx * 128 >= (NPC + 1) / 2) return;

    const int pair = bx * 128 + tid;
    const int p0 = pair*2, p1 = p0 + 1;
    const bool v0 = p0 < NPC, v1 = p1 < NPC;
    const int cr0 = v0 ? p0 / CXN : 0, cc0_ = v0 ? p0 % CXN : 0;
    const int cr1 = v1 ? p1 / CXN : 0, cc1_ = v1 ? p1 % CXN : 0;

    bool ok0[NT], ok1[NT];
    int  io0[NT], io1[NT];
    #pragma unroll
    for (int tt = 0; tt < NT; tt++) {
        int th = tt / NTW, tw = tt % NTW;
        int iy0 = cr0 - th, ix0 = cc0_ - tw;
        ok0[tt] = v0 && iy0 >= 0 && iy0 < HX && ix0 >= 0 && ix0 < HX;
        io0[tt] = iy0 * HX + ix0;
        int iy1 = cr1 - th, ix1 = cc1_ - tw;
        ok1[tt] = v1 && iy1 >= 0 && iy1 < HX && ix1 >= 0 && ix1 < HX;
        io1[tt] = iy1 * HX + ix1;
    }

    ull accA[8], accB[8];
    #pragma unroll
    for (int i = 0; i < 8; i++) { accA[i] = 0ull; accB[i] = 0ull; }

    const float* xb = x + (size_t)b * CX * HX * HX;

    for (int cc = 0; cc < CX; cc += 32) {
        __syncthreads();
        for (int i = tid; i < 16*32*NT; i += 128) {
            int tt = i % NT;
            int ci = (i / NT) & 31;
            int co = i / (NT * 32);
            int th = tt / NTW, tw = tt % NTW;
            int kh = (NTH == 2) ? 2*th : 1;
            int kw = (NTW == 2) ? 2*tw : 1;
            ((float*)swt)[((ci*8 + (co>>1))*NT + tt)*2 + (co&1)] =
                Wt[((size_t)(co0 + co)*CX + cc + ci)*9 + kh*3 + kw];
        }
        __syncthreads();

        #pragma unroll 1
        for (int ci = 0; ci < 32; ci++) {
            const float* pl = xb + (size_t)(cc + ci) * (HX * HX);
            ull in0[NT], in1[NT];
            #pragma unroll
            for (int tt = 0; tt < NT; tt++) {
                float a  = ok0[tt] ? __ldg(pl + io0[tt]) : 0.f;
                float bb = ok1[tt] ? __ldg(pl + io1[tt]) : 0.f;
                in0[tt] = bcast2(a);
                in1[tt] = bcast2(bb);
            }
            const ull* wbase = swt + ci * 8 * NT;
            #pragma unroll
            for (int cop = 0; cop < 8; cop++) {
                ull w[NT];
                if constexpr (NT == 4) {
                    const ulonglong2* qq = (const ulonglong2*)(wbase + cop*4);
                    ulonglong2 q0 = qq[0], q1 = qq[1];
                    w[0] = q0.x; w[1] = q0.y; w[2] = q1.x; w[3] = q1.y;
                } else if constexpr (NT == 2) {
                    ulonglong2 q0 = ((const ulonglong2*)(wbase + cop*2))[0];
                    w[0] = q0.x; w[1] = q0.y;
                } else {
                    w[0] = wbase[cop];
                }
                ull a = accA[cop], bb2 = accB[cop];
                #pragma unroll
                for (int tt = 0; tt < NT; tt++) {
                    a   = fma2(w[tt], in0[tt], a);
                    bb2 = fma2(w[tt], in1[tt], bb2);
                }
                accA[cop] = a; accB[cop] = bb2;
            }
        }
    }

    const int oy0 = 2*cr0 + PY, ox0 = 2*cc0_ + PXP;
    const int oy1 = 2*cr1 + PY, ox1 = 2*cc1_ + PXP;
    #pragma unroll
    for (int cop = 0; cop < 8; cop++) {
        float a0, a1, b0, b1;
        unpack2(accA[cop], a0, a1);
        unpack2(accB[cop], b0, b1);
        int coA = co0 + 2*cop, coB = coA + 1;
        float bA = __ldg(bt + coA), bB = __ldg(bt + coB);
        if (v0) {
            size_t qq = HDR + ((size_t)b*CX + coA)*PSTR + oy0*PP + ox0;
            g_h[qq]        = fmaxf(a0 + bA, 0.f);
            g_h[qq + PSTR] = fmaxf(a1 + bB, 0.f);
        }
        if (v1) {
            size_t qq = HDR + ((size_t)b*CX + coA)*PSTR + oy1*PP + ox1;
            g_h[qq]        = fmaxf(b0 + bA, 0.f);
            g_h[qq + PSTR] = fmaxf(b1 + bB, 0.f);
        }
    }
}

__global__ void __launch_bounds__(128, 5) convt_all(
    const float* __restrict__ x, const float* __restrict__ Wt,
    const float* __restrict__ bt)
{
    __shared__ __align__(16) ull swt[32 * 8 * 4];
    // zero BN stats from the first grid block (runs before any conv layer)
    if (blockIdx.x == 0 && blockIdx.y == 0 && blockIdx.z == 0) {
        for (int i = threadIdx.x; i < 4*2*CG; i += 128) g_stats[i] = 0.f;
    }
    const int b   = blockIdx.z >> 2;
    const int cls = blockIdx.z & 3;
    const int co0 = blockIdx.y * 16;
    const int tid = threadIdx.x;
    const int bx  = blockIdx.x;
    switch (cls) {
        case 0: convt_body<2,2>(x, Wt, bt, swt, b, co0, bx, tid); break;
        case 1: convt_body<2,1>(x, Wt, bt, swt, b, co0, bx, tid); break;
        case 2: convt_body<1,2>(x, Wt, bt, swt, b, co0, bx, tid); break;
        default: convt_body<1,1>(x, Wt, bt, swt, b, co0, bx, tid); break;
    }
}

// ---------------- fused gate ------------
__global__ void gate_kernel(const float* __restrict__ y,
                            const float* __restrict__ Wq,
                            const float* __restrict__ bq,
                            const float* __restrict__ Wv,
                            const float* __restrict__ bv) {
    __shared__ float swv[KD], sbv[KD], swq[9];
    __shared__ float sbq;
    int tid = threadIdx.x;
    int zc = blockIdx.y;
    int c  = zc % CG;
    int b  = zc / CG;
    if (tid < KD) { swv[tid] = Wv[tid]; sbv[tid] = bv[tid]; }
    if (tid < 9)  swq[tid] = Wq[c * 9 + tid];
    if (tid == 9) sbq = bq[c];
    __syncthreads();

    int pix = blockIdx.x * 256 + tid;
    if (pix >= NPIX) return;
    int oy = pix / HY, ox = pix % HY;

    const float* p = y + ((size_t)b * CG + c) * NPIX;
    float qv = sbq;
    #pragma unroll
    for (int ky = 0; ky < 3; ky++) {
        int iy = oy + ky - 1;
        if (iy < 0 || iy >= HY) continue;
        #pragma unroll
        for (int kx = 0; kx < 3; kx++) {
            int ix = ox + kx - 1;
            if (ix < 0 || ix >= HY) continue;
            qv += __ldg(p + iy * HY + ix) * swq[ky * 3 + kx];
        }
    }
    qv = fmaxf(qv, 0.f);

    float yv = __ldg(p + pix);
    const float* kp = g_k + HDR + (size_t)b * KD * PSTR + oy*PP + ox;

    float s[KD];
    float mx = -1e30f;
    #pragma unroll
    for (int d = 0; d < KD; d++) {
        s[d] = qv * __ldg(kp + (size_t)d * PSTR);
        mx = fmaxf(mx, s[d]);
    }
    float se = 0.f, num = 0.f;
    #pragma unroll
    for (int d = 0; d < KD; d++) {
        float e = __expf(s[d] - mx);
        se  += e;
        num += e * fmaxf(yv * swv[d] + sbv[d], 0.f);
    }
    g_g[HDR + ((size_t)b * CG + c) * PSTR + oy*PP + ox] = num / se;
}

// ---------------- host launch -----------------------------------------------
extern "C" void kernel_launch(void* const* d_in, const int* in_sizes, int n_in,
                              void* d_out, int out_size) {
    const float* x  = (const float*)d_in[0];
    const float* y  = (const float*)d_in[1];
    const float* Wt = (const float*)d_in[2];
    const float* bt = (const float*)d_in[3];
    const float* W1 = (const float*)d_in[4];
    const float* g1 = (const float*)d_in[5];
    const float* b1 = (const float*)d_in[6];
    const float* W2 = (const float*)d_in[7];
    const float* g2 = (const float*)d_in[8];
    const float* b2 = (const float*)d_in[9];
    const float* Wq = (const float*)d_in[10];
    const float* bq = (const float*)d_in[11];
    const float* Wk = (const float*)d_in[12];
    const float* bk = (const float*)d_in[13];
    const float* Wv = (const float*)d_in[14];
    const float* bv = (const float*)d_in[15];
    const float* W3 = (const float*)d_in[16];
    const float* g3 = (const float*)d_in[17];
    const float* b3 = (const float*)d_in[18];
    const float* W4 = (const float*)d_in[19];
    const float* g4 = (const float*)d_in[20];
    const float* b4 = (const float*)d_in[21];
    float* out = (float*)d_out;

    float *p_h, *p_tmp, *p_a, *p_xu, *p_k, *p_g, *p_o1, *p_stats;
    cudaGetSymbolAddress((void**)&p_h,     g_h);
    cudaGetSymbolAddress((void**)&p_tmp,   g_tmp);
    cudaGetSymbolAddress((void**)&p_a,     g_a);
    cudaGetSymbolAddress((void**)&p_xu,    g_xu);
    cudaGetSymbolAddress((void**)&p_k,     g_k);
    cudaGetSymbolAddress((void**)&p_g,     g_g);
    cudaGetSymbolAddress((void**)&p_o1,    g_o1);
    cudaGetSymbolAddress((void**)&p_stats, g_stats);

    const int BJ = (JOBS5 + 127) / 128;     // 9
    dim3 grdS (BJ, CG/8, BB*2);             // split conv1: 1152 blocks
    dim3 grdCG(BJ, CG/8, BB);               // unsplit CG convs: 576 blocks
    dim3 grdKQ(BJ, KD/8, BB*4);             // split-4 K conv: 576 blocks
    int  elems  = BB * CG * NPIX;
    int  eb     = (elems + 255) / 256;
    int  planes = BB * CG;
    int  padBlocks = (planes * CHUNKS + 255) / 256;
    int  kBlocks   = (BB * KD * CHUNKS + 255) / 256;

    convt_all<<<dim3(5, CX/16, BB*4), 128>>>(x, Wt, bt);

    // conv1 (256 -> 128): split-K(2) + prefetch
    conv3x3_v5sp<128><<<grdS, 128>>>(p_h, W1, p_tmp, p_o1, CG);
    sum_stats_v2<<<planes, 256>>>(p_tmp, p_o1, p_stats + 0);
    bn_relu_pad<<<padBlocks, 256>>>(p_tmp, p_stats + 0, g1, b1, p_a);

    // conv2: unsplit + prefetch, fused stats
    conv3x3_v5p<CG, false, true, false><<<grdCG, 128>>>(p_a, W2, nullptr, p_tmp, p_stats + 2*CG, CG);
    bn_relu_pad<<<padBlocks, 256>>>(p_tmp, p_stats + 2*CG, g2, b2, p_xu);

    // K conv: split-K(4) + prefetch, then combine + gate
    conv3x3_v5qp<<<grdKQ, 128>>>(p_xu, Wk, p_tmp);
    combine_k<<<kBlocks, 256>>>(p_tmp, bk, p_k);
    gate_kernel<<<dim3((NPIX + 255)/256, BB*CG), 256>>>(y, Wq, bq, Wv, bv);

    // final DoubleConv
    conv3x3_v5p<CG, false, true, false><<<grdCG, 128>>>(p_g, W3, nullptr, p_tmp, p_stats + 4*CG, CG);
    bn_relu_pad<<<padBlocks, 256>>>(p_tmp, p_stats + 4*CG, g3, b3, p_o1);
    conv3x3_v5p<CG, false, true, false><<<grdCG, 128>>>(p_o1, W4, nullptr, p_tmp, p_stats + 6*CG, CG);
    bn_relu_out<<<eb, 256>>>(p_tmp, p_stats + 6*CG, g4, b4, out);
}